// round 6
// baseline (speedup 1.0000x reference)
#include <cuda_runtime.h>
#include <cuda_bf16.h>
#include <math.h>
#include <stdint.h>

#define CDIM   512
#define NHEADS 8
#define DH     64
#define NWIN   32
#define SLEN   512
#define MROWS  (NWIN*SLEN)   // 16384

// ------------------------- device scratch (no allocs) -------------------------
__device__ __align__(16) __nv_bfloat16 g_xhi[MROWS*CDIM];
__device__ __align__(16) __nv_bfloat16 g_xlo[MROWS*CDIM];
__device__ __align__(16) __nv_bfloat16 g_atthi[MROWS*CDIM];
__device__ __align__(16) __nv_bfloat16 g_attlo[MROWS*CDIM];
__device__ __align__(16) __nv_bfloat16 g_Bhi[2048*CDIM];   // 0..1535 [Wq|Wk|Wv]^T (n,k), 1536..2047 Wo^T
__device__ __align__(16) __nv_bfloat16 g_Blo[2048*CDIM];
// split-bf16 Q,K: [nh][s][d];  V transposed: [nh][d][t]
__device__ __align__(16) __nv_bfloat16 g_Qh[NWIN*NHEADS*SLEN*DH];
__device__ __align__(16) __nv_bfloat16 g_Ql[NWIN*NHEADS*SLEN*DH];
__device__ __align__(16) __nv_bfloat16 g_Kh[NWIN*NHEADS*SLEN*DH];
__device__ __align__(16) __nv_bfloat16 g_Kl[NWIN*NHEADS*SLEN*DH];
__device__ __align__(16) __nv_bfloat16 g_Vth[NWIN*NHEADS*DH*SLEN];
__device__ __align__(16) __nv_bfloat16 g_Vtl[NWIN*NHEADS*DH*SLEN];
__device__ float g_tabc[16*SLEN];
__device__ float g_tabs[16*SLEN];

// ------------------------- helpers -------------------------
__device__ __forceinline__ uint32_t smem_u32(const void* p) {
    uint32_t a;
    asm("{ .reg .u64 t; cvta.to.shared.u64 t, %1; cvt.u32.u64 %0, t; }" : "=r"(a) : "l"(p));
    return a;
}
__device__ __forceinline__ void cpasync16(uint32_t dst, const void* src) {
    asm volatile("cp.async.cg.shared.global [%0], [%1], 16;" :: "r"(dst), "l"(src) : "memory");
}
#define CP_COMMIT() asm volatile("cp.async.commit_group;" ::: "memory")
#define CP_WAIT(n)  asm volatile("cp.async.wait_group %0;" :: "n"(n) : "memory")

__device__ __forceinline__ void ldm_x4(uint32_t& r0, uint32_t& r1, uint32_t& r2, uint32_t& r3, uint32_t a) {
    asm volatile("ldmatrix.sync.aligned.m8n8.x4.shared.b16 {%0,%1,%2,%3}, [%4];"
                 : "=r"(r0), "=r"(r1), "=r"(r2), "=r"(r3) : "r"(a));
}
__device__ __forceinline__ void mma16816(float* d, const uint32_t* a, const uint32_t* b) {
    asm volatile(
        "mma.sync.aligned.m16n8k16.row.col.f32.bf16.bf16.f32 "
        "{%0,%1,%2,%3}, {%4,%5,%6,%7}, {%8,%9}, {%0,%1,%2,%3};"
        : "+f"(d[0]), "+f"(d[1]), "+f"(d[2]), "+f"(d[3])
        : "r"(a[0]), "r"(a[1]), "r"(a[2]), "r"(a[3]), "r"(b[0]), "r"(b[1]));
}
__device__ __forceinline__ uint32_t pack_bf16(__nv_bfloat16 a, __nv_bfloat16 b) {
    return ((uint32_t)__bfloat16_as_ushort(b) << 16) | __bfloat16_as_ushort(a);
}
__device__ __forceinline__ void split2(float v, __nv_bfloat16& h, __nv_bfloat16& l) {
    h = __float2bfloat16(v);
    l = __float2bfloat16(v - __bfloat162float(h));
}

// ------------------------- fused prep kernel -------------------------
// blocks [0,8192): x gather+split; [8192,12288): W transpose+split; [12288,12320): rotary table
__global__ __launch_bounds__(256) void prep_all_kernel(
    const float* __restrict__ x,
    const float* __restrict__ Wq, const float* __restrict__ Wk,
    const float* __restrict__ Wv, const float* __restrict__ Wo)
{
    const int gb = blockIdx.x;
    if (gb < 8192) {
        int idx = gb * 256 + threadIdx.x;
        int m = idx >> 7;
        int k4 = (idx & 127) << 2;
        int nwin = m >> 9, s = m & 511;
        int b = nwin & 1, wb = (nwin >> 1) & 3, hb = nwin >> 3;
        int f = s >> 6, r = (s >> 3) & 7, cc = s & 7;
        const float* src = x + (size_t)((((b*8 + f)*32 + hb*8 + r)*32 + wb*8 + cc)) * CDIM + k4;
        float4 v = *(const float4*)src;
        __nv_bfloat16 h0,h1,h2,h3,l0,l1,l2,l3;
        split2(v.x,h0,l0); split2(v.y,h1,l1); split2(v.z,h2,l2); split2(v.w,h3,l3);
        uint2 hv = { pack_bf16(h0, h1), pack_bf16(h2, h3) };
        uint2 lv = { pack_bf16(l0, l1), pack_bf16(l2, l3) };
        *(uint2*)(g_xhi + (size_t)m * CDIM + k4) = hv;
        *(uint2*)(g_xlo + (size_t)m * CDIM + k4) = lv;
    } else if (gb < 12288) {
        int idx = (gb - 8192) * 256 + threadIdx.x;   // 2048*512
        int n = idx & 511;
        int km = idx >> 9;
        int mat = km >> 9, k = km & 511;
        const float* W = (mat == 0) ? Wq : (mat == 1) ? Wk : (mat == 2) ? Wv : Wo;
        float v = W[(size_t)k * CDIM + n];
        __nv_bfloat16 h, l;
        split2(v, h, l);
        size_t dst = (size_t)(mat * 512 + n) * CDIM + k;
        g_Bhi[dst] = h;
        g_Blo[dst] = l;
    } else {
        int idx = (gb - 12288) * 256 + threadIdx.x;
        if (idx < 16 * SLEN) {
            int jj = idx >> 9, s = idx & 511;
            const float LN = 0.5756462732485114210f;    // ln(10000)/16
            float ang = (float)s * expf(-LN * (float)jj);
            float sn, cs;
            sincosf(ang, &sn, &cs);
            g_tabc[idx] = cs;
            g_tabs[idx] = sn;
        }
    }
}

// ------------------------- mma.sync GEMM (3-stage, BK=64) -------------------------
#define BM 128
#define BN 128
#define BK 64
#define ROWB 144              // 128B data + 16B pad: conflict-free ldmatrix
#define PLSTG (128*ROWB)      // 18432 one plane (128 rows)
#define STAGE (4*PLSTG)       // A(2pl)+B(2pl) = 73728
#define SA_OFF(st, pl) ((st)*STAGE + (pl)*PLSTG)
#define SB_OFF(st, pl) ((st)*STAGE + 2*PLSTG + (pl)*PLSTG)
#define SMEM_TOTAL (3*STAGE)  // 221184

template<int MODE>
__global__ __launch_bounds__(256) void gemm_kernel(float* __restrict__ out,
                                                   const float* __restrict__ bo)
{
    extern __shared__ char smem[];
    const uint32_t sb = smem_u32(smem);
    const int tid  = threadIdx.x;
    const int lane = tid & 31;
    const int wid  = tid >> 5;
    const int warpM = wid >> 1;
    const int warpN = wid & 1;
    const int gid = lane >> 2;
    const int tig = lane & 3;
    const int lrow = lane & 15;
    const int lside = lane >> 4;

    const int m0 = blockIdx.y * BM;
    const int n0 = blockIdx.x * BN;
    const int nrow0 = MODE ? (1536 + n0) : n0;
    const __nv_bfloat16* Ah = MODE ? g_atthi : g_xhi;
    const __nv_bfloat16* Al = MODE ? g_attlo : g_xlo;

    float acc[2][8][4];
#pragma unroll
    for (int i = 0; i < 2; i++)
#pragma unroll
        for (int j = 0; j < 8; j++)
#pragma unroll
            for (int t = 0; t < 4; t++) acc[i][j][t] = 0.f;

    auto load_chunk = [&](int c, int st) {
        const int k0 = c * BK;
#pragma unroll
        for (int i = tid; i < 2048; i += 256) {       // A: 2pl x 128 rows x 8 chunks16B
            int pl = i >> 10, rr = (i >> 3) & 127, ch = i & 7;
            const __nv_bfloat16* src = (pl ? Al : Ah) + (size_t)(m0 + rr) * CDIM + k0 + ch * 8;
            cpasync16(sb + SA_OFF(st, pl) + rr * ROWB + ch * 16, src);
        }
#pragma unroll
        for (int i = tid; i < 2048; i += 256) {       // B: 2pl x 128 rows x 8
            int pl = i >> 10, rr = (i >> 3) & 127, ch = i & 7;
            const __nv_bfloat16* src = (pl ? g_Blo : g_Bhi) + (size_t)(nrow0 + rr) * CDIM + k0 + ch * 8;
            cpasync16(sb + SB_OFF(st, pl) + rr * ROWB + ch * 16, src);
        }
        CP_COMMIT();
    };

    load_chunk(0, 0);
    load_chunk(1, 1);

    const int NCH = CDIM / BK;   // 8

    for (int c = 0; c < NCH; c++) {
        if (c == NCH - 1) CP_WAIT(0); else CP_WAIT(1);
        __syncthreads();
        if (c + 2 < NCH) load_chunk(c + 2, (c + 2) % 3);
        const int st = c % 3;
#pragma unroll
        for (int k4 = 0; k4 < 4; k4++) {
            const int kb = k4 * 32 + lside * 16;
            uint32_t ah[2][4], al_[2][4];
#pragma unroll
            for (int mt = 0; mt < 2; mt++) {
                ldm_x4(ah[mt][0], ah[mt][1], ah[mt][2], ah[mt][3],
                       sb + SA_OFF(st, 0) + (warpM*32 + mt*16 + lrow) * ROWB + kb);
                ldm_x4(al_[mt][0], al_[mt][1], al_[mt][2], al_[mt][3],
                       sb + SA_OFF(st, 1) + (warpM*32 + mt*16 + lrow) * ROWB + kb);
            }
            uint32_t bh[8][2], bl_[8][2];
#pragma unroll
            for (int ntp = 0; ntp < 4; ntp++) {
                ldm_x4(bh[2*ntp][0], bh[2*ntp+1][0], bh[2*ntp][1], bh[2*ntp+1][1],
                       sb + SB_OFF(st, 0) + (warpN*64 + ntp*16 + lrow) * ROWB + kb);
                ldm_x4(bl_[2*ntp][0], bl_[2*ntp+1][0], bl_[2*ntp][1], bl_[2*ntp+1][1],
                       sb + SB_OFF(st, 1) + (warpN*64 + ntp*16 + lrow) * ROWB + kb);
            }
            // plane-outer ordering: no back-to-back same-accumulator MMAs
#pragma unroll
            for (int mt = 0; mt < 2; mt++)
#pragma unroll
                for (int nt = 0; nt < 8; nt++) mma16816(acc[mt][nt], ah[mt], bh[nt]);
#pragma unroll
            for (int mt = 0; mt < 2; mt++)
#pragma unroll
                for (int nt = 0; nt < 8; nt++) mma16816(acc[mt][nt], al_[mt], bh[nt]);
#pragma unroll
            for (int mt = 0; mt < 2; mt++)
#pragma unroll
                for (int nt = 0; nt < 8; nt++) mma16816(acc[mt][nt], ah[mt], bl_[nt]);
        }
    }

    const int mwbase = m0 + warpM * 32;
    const int cwbase = n0 + warpN * 64;

#pragma unroll
    for (int mt = 0; mt < 2; mt++) {
#pragma unroll
        for (int nt = 0; nt < 8; nt++) {
            const int g = cwbase + nt * 8 + tig * 2;
            if (MODE == 0) {
                const int mat = g >> 9;
                const int cc = g & 511;
                const int head = cc >> 6;
                const int d = cc & 63;
#pragma unroll
                for (int half = 0; half < 2; half++) {
                    const int row = mwbase + mt * 16 + gid + half * 8;
                    const int nw = row >> 9;
                    const int s  = row & 511;
                    float v0 = acc[mt][nt][half * 2];
                    float v1 = acc[mt][nt][half * 2 + 1];
                    if (mat < 2 && d < 32) {
                        const int j0 = d >> 1;
                        float cs = g_tabc[j0 * 512 + s];
                        float sn = g_tabs[j0 * 512 + s];
                        float w0 = v0 * cs - v1 * sn;
                        float w1 = v1 * cs + v0 * sn;
                        v0 = w0; v1 = w1;
                    }
                    __nv_bfloat16 h0,h1,l0,l1;
                    split2(v0,h0,l0); split2(v1,h1,l1);
                    const int nhh = nw * NHEADS + head;
                    if (mat == 0) {
                        size_t base = ((size_t)nhh * SLEN + s) * DH + d;
                        *(uint32_t*)(g_Qh + base) = pack_bf16(h0, h1);
                        *(uint32_t*)(g_Ql + base) = pack_bf16(l0, l1);
                    } else if (mat == 1) {
                        size_t base = ((size_t)nhh * SLEN + s) * DH + d;
                        *(uint32_t*)(g_Kh + base) = pack_bf16(h0, h1);
                        *(uint32_t*)(g_Kl + base) = pack_bf16(l0, l1);
                    } else {
                        size_t vb = ((size_t)nhh * DH + d) * SLEN + s;
                        g_Vth[vb] = h0; g_Vth[vb + SLEN] = h1;
                        g_Vtl[vb] = l0; g_Vtl[vb + SLEN] = l1;
                    }
                }
            } else {
                const float2 bias = *(const float2*)(bo + g);
#pragma unroll
                for (int half = 0; half < 2; half++) {
                    const int row = mwbase + mt * 16 + gid + half * 8;
                    const int nwv = row >> 9, ss = row & 511;
                    const int b = nwv & 1, wb = (nwv >> 1) & 3, hb = nwv >> 3;
                    const int fr = ss >> 6, rr = (ss >> 3) & 7, c2 = ss & 7;
                    const size_t obase = ((size_t)b * (8*32*32) + (size_t)fr * (32*32)
                                        + (size_t)(hb*8 + rr) * 32 + (wb*8 + c2)) * CDIM;
                    float2 v = { acc[mt][nt][half*2] + bias.x,
                                 acc[mt][nt][half*2 + 1] + bias.y };
                    *(float2*)(out + obase + g) = v;
                }
            }
        }
    }
}

// ------------------------- tensor-core flash attention (3-stage KV) -------------------------
#define AP 144
#define QPL (128*AP)                         // 18432
#define KVSTG (4*64*AP)                      // 36864 per stage (K 2pl + V 2pl)
#define SQ_OFF(pl)       ((pl) * QPL)
#define SK_OFF(st, pl)   (2*QPL + (st)*KVSTG + (pl)*(64*AP))
#define SV_OFF(st, pl)   (2*QPL + (st)*KVSTG + 2*(64*AP) + (pl)*(64*AP))
#define SP_OFF(pl)       (2*QPL + 3*KVSTG + (pl)*QPL)
#define ATTN_SMEM        (2*QPL + 3*KVSTG + 2*QPL)   // 184320

__global__ __launch_bounds__(256) void attn_kernel()
{
    extern __shared__ char smem[];
    const uint32_t sb = smem_u32(smem);
    const int qt = blockIdx.x;
    const int nh = blockIdx.y;
    const int tid = threadIdx.x;
    const int lane = tid & 31;
    const int wid = tid >> 5;
    const int gid = lane >> 2;
    const int tig = lane & 3;
    const int lrow = lane & 15;
    const int lside = lane >> 4;

    // Q tile (128 x 64, 2 planes)
    {
        const size_t qbase = ((size_t)nh * SLEN + qt * 128) * DH;
#pragma unroll
        for (int i = tid; i < 2048; i += 256) {
            int pl = i >> 10, r = (i >> 3) & 127, ch = i & 7;
            const __nv_bfloat16* src = (pl ? g_Ql : g_Qh) + qbase + (size_t)r * DH + ch * 8;
            cpasync16(sb + SQ_OFF(pl) + r * AP + ch * 16, src);
        }
        CP_COMMIT();
    }

    const int nkt = 2 * qt + 2;

    auto load_kv = [&](int kt, int st) {
#pragma unroll
        for (int i = tid; i < 2048; i += 256) {
            if (i < 1024) {
                int pl = i >> 9, r = (i >> 3) & 63, ch = i & 7;
                const __nv_bfloat16* src = (pl ? g_Kl : g_Kh)
                    + ((size_t)nh * SLEN + kt * 64 + r) * DH + ch * 8;
                cpasync16(sb + SK_OFF(st, pl) + r * AP + ch * 16, src);
            } else {
                int j = i - 1024;
                int pl = j >> 9, r = (j >> 3) & 63, ch = j & 7;
                const __nv_bfloat16* src = (pl ? g_Vtl : g_Vth)
                    + ((size_t)nh * DH + r) * SLEN + kt * 64 + ch * 8;
                cpasync16(sb + SV_OFF(st, pl) + r * AP + ch * 16, src);
            }
        }
        CP_COMMIT();
    };

    load_kv(0, 0);
    if (nkt > 1) load_kv(1, 1);

    float accO[8][4];
#pragma unroll
    for (int j = 0; j < 8; j++)
#pragma unroll
        for (int t = 0; t < 4; t++) accO[j][t] = 0.f;
    float lsum0 = 0.f, lsum1 = 0.f;

    const int qrow0 = qt * 128 + wid * 16;

    for (int kt = 0; kt < nkt; kt++) {
        if (kt == nkt - 1) CP_WAIT(0); else CP_WAIT(1);
        __syncthreads();
        if (kt + 2 < nkt) load_kv(kt + 2, (kt + 2) % 3);
        const int st = kt % 3;

        // ---- S = Q K^T (3 planes) ----
        float accS[8][4];
#pragma unroll
        for (int j = 0; j < 8; j++)
#pragma unroll
            for (int t = 0; t < 4; t++) accS[j][t] = 0.f;

#pragma unroll
        for (int k4 = 0; k4 < 4; k4++) {
            const int kb = k4 * 32 + lside * 16;
            uint32_t qh[4], ql[4];
            ldm_x4(qh[0], qh[1], qh[2], qh[3], sb + SQ_OFF(0) + (wid*16 + lrow) * AP + kb);
            ldm_x4(ql[0], ql[1], ql[2], ql[3], sb + SQ_OFF(1) + (wid*16 + lrow) * AP + kb);
            uint32_t kh[8][2], kl_[8][2];
#pragma unroll
            for (int ntp = 0; ntp < 4; ntp++) {
                ldm_x4(kh[2*ntp][0], kh[2*ntp+1][0], kh[2*ntp][1], kh[2*ntp+1][1],
                       sb + SK_OFF(st, 0) + (ntp*16 + lrow) * AP + kb);
                ldm_x4(kl_[2*ntp][0], kl_[2*ntp+1][0], kl_[2*ntp][1], kl_[2*ntp+1][1],
                       sb + SK_OFF(st, 1) + (ntp*16 + lrow) * AP + kb);
            }
#pragma unroll
            for (int nt = 0; nt < 8; nt++) mma16816(accS[nt], qh, kh[nt]);
#pragma unroll
            for (int nt = 0; nt < 8; nt++) mma16816(accS[nt], ql, kh[nt]);
#pragma unroll
            for (int nt = 0; nt < 8; nt++) mma16816(accS[nt], qh, kl_[nt]);
        }

        // ---- exp + causal + l + split-bf16 P (warp-private rows) ----
#pragma unroll
        for (int nt = 0; nt < 8; nt++) {
#pragma unroll
            for (int half = 0; half < 2; half++) {
                const int row = qrow0 + gid + half * 8;
                const int col0 = kt * 64 + nt * 8 + tig * 2;
                float s0 = accS[nt][half*2]     * 0.125f;
                float s1 = accS[nt][half*2 + 1] * 0.125f;
                float p0 = (col0     <= row) ? __expf(s0) : 0.f;
                float p1 = (col0 + 1 <= row) ? __expf(s1) : 0.f;
                if (half) lsum1 += p0 + p1; else lsum0 += p0 + p1;
                __nv_bfloat16 h0,h1,l0,l1;
                split2(p0,h0,l0); split2(p1,h1,l1);
                uint32_t off = (wid*16 + gid + half*8) * AP + (nt*8 + tig*2) * 2;
                *(uint32_t*)(smem + SP_OFF(0) + off) = pack_bf16(h0, h1);
                *(uint32_t*)(smem + SP_OFF(1) + off) = pack_bf16(l0, l1);
            }
        }
        __syncwarp();   // P rows are warp-private: warp-level visibility suffices

        // ---- O += P V (3 planes) ----
#pragma unroll
        for (int k4 = 0; k4 < 4; k4++) {
            const int kb = k4 * 32 + lside * 16;
            uint32_t ph[4], pl_[4];
            ldm_x4(ph[0], ph[1], ph[2], ph[3], sb + SP_OFF(0) + (wid*16 + lrow) * AP + kb);
            ldm_x4(pl_[0], pl_[1], pl_[2], pl_[3], sb + SP_OFF(1) + (wid*16 + lrow) * AP + kb);
            uint32_t vh[8][2], vl_[8][2];
#pragma unroll
            for (int ntp = 0; ntp < 4; ntp++) {
                ldm_x4(vh[2*ntp][0], vh[2*ntp+1][0], vh[2*ntp][1], vh[2*ntp+1][1],
                       sb + SV_OFF(st, 0) + (ntp*16 + lrow) * AP + kb);
                ldm_x4(vl_[2*ntp][0], vl_[2*ntp+1][0], vl_[2*ntp][1], vl_[2*ntp+1][1],
                       sb + SV_OFF(st, 1) + (ntp*16 + lrow) * AP + kb);
            }
#pragma unroll
            for (int nt = 0; nt < 8; nt++) mma16816(accO[nt], ph,  vh[nt]);
#pragma unroll
            for (int nt = 0; nt < 8; nt++) mma16816(accO[nt], pl_, vh[nt]);
#pragma unroll
            for (int nt = 0; nt < 8; nt++) mma16816(accO[nt], ph,  vl_[nt]);
        }
    }

    // ---- finalize ----
    lsum0 += __shfl_xor_sync(0xFFFFFFFF, lsum0, 1);
    lsum0 += __shfl_xor_sync(0xFFFFFFFF, lsum0, 2);
    lsum1 += __shfl_xor_sync(0xFFFFFFFF, lsum1, 1);
    lsum1 += __shfl_xor_sync(0xFFFFFFFF, lsum1, 2);
    const float inv0 = 1.f / lsum0;
    const float inv1 = 1.f / lsum1;

    const int nwn = nh >> 3, hh = nh & 7;
#pragma unroll
    for (int half = 0; half < 2; half++) {
        const int srow = qrow0 + gid + half * 8;
        const float inv = half ? inv1 : inv0;
        const size_t mrow = (size_t)nwn * SLEN + srow;
#pragma unroll
        for (int nt = 0; nt < 8; nt++) {
            const int d = nt * 8 + tig * 2;
            float v0 = accO[nt][half*2]     * inv;
            float v1 = accO[nt][half*2 + 1] * inv;
            __nv_bfloat16 h0,h1,l0,l1;
            split2(v0,h0,l0); split2(v1,h1,l1);
            size_t base = mrow * CDIM + hh * DH + d;
            *(uint32_t*)(g_atthi + base) = pack_bf16(h0, h1);
            *(uint32_t*)(g_attlo + base) = pack_bf16(l0, l1);
        }
    }
}

// ------------------------- launch -------------------------
extern "C" void kernel_launch(void* const* d_in, const int* in_sizes, int n_in,
                              void* d_out, int out_size)
{
    const float* x  = (const float*)d_in[0];
    const float* Wq = (const float*)d_in[1];
    const float* Wk = (const float*)d_in[2];
    const float* Wv = (const float*)d_in[3];
    const float* Wo = (const float*)d_in[4];
    const float* bo = (const float*)d_in[5];
    float* out = (float*)d_out;
    (void)in_sizes; (void)n_in; (void)out_size;

    static bool attr_done = false;
    if (!attr_done) {
        cudaFuncSetAttribute(gemm_kernel<0>, cudaFuncAttributeMaxDynamicSharedMemorySize, SMEM_TOTAL);
        cudaFuncSetAttribute(gemm_kernel<1>, cudaFuncAttributeMaxDynamicSharedMemorySize, SMEM_TOTAL);
        cudaFuncSetAttribute(attn_kernel, cudaFuncAttributeMaxDynamicSharedMemorySize, ATTN_SMEM);
        attr_done = true;
    }

    prep_all_kernel<<<12320, 256>>>(x, Wq, Wk, Wv, Wo);

    dim3 gq(12, MROWS / BM);             // N=1536
    gemm_kernel<0><<<gq, 256, SMEM_TOTAL>>>(nullptr, nullptr);

    dim3 ga(4, NWIN * NHEADS);
    attn_kernel<<<ga, 256, ATTN_SMEM>>>();

    dim3 go(4, MROWS / BM);              // N=512
    gemm_kernel<1><<<go, 256, SMEM_TOTAL>>>(out, bo);
}

// round 7
// speedup vs baseline: 1.1661x; 1.1661x over previous
#include <cuda_runtime.h>
#include <cuda_bf16.h>
#include <math.h>
#include <stdint.h>

#define CDIM   512
#define NHEADS 8
#define DH     64
#define NWIN   32
#define SLEN   512
#define MROWS  (NWIN*SLEN)   // 16384

// ------------------------- device scratch (no allocs) -------------------------
__device__ __align__(16) __nv_bfloat16 g_xhi[MROWS*CDIM];
__device__ __align__(16) __nv_bfloat16 g_xlo[MROWS*CDIM];
__device__ __align__(16) __nv_bfloat16 g_atthi[MROWS*CDIM];
__device__ __align__(16) __nv_bfloat16 g_attlo[MROWS*CDIM];
__device__ __align__(16) __nv_bfloat16 g_Bhi[2048*CDIM];   // 0..1535 [Wq|Wk|Wv]^T (n,k), 1536..2047 Wo^T
__device__ __align__(16) __nv_bfloat16 g_Blo[2048*CDIM];
// split-bf16 Q,K: [nh][s][d];  V transposed: [nh][d][t]
__device__ __align__(16) __nv_bfloat16 g_Qh[NWIN*NHEADS*SLEN*DH];
__device__ __align__(16) __nv_bfloat16 g_Ql[NWIN*NHEADS*SLEN*DH];
__device__ __align__(16) __nv_bfloat16 g_Kh[NWIN*NHEADS*SLEN*DH];
__device__ __align__(16) __nv_bfloat16 g_Kl[NWIN*NHEADS*SLEN*DH];
__device__ __align__(16) __nv_bfloat16 g_Vth[NWIN*NHEADS*DH*SLEN];
__device__ __align__(16) __nv_bfloat16 g_Vtl[NWIN*NHEADS*DH*SLEN];
__device__ float g_tabc[16*SLEN];
__device__ float g_tabs[16*SLEN];

// ------------------------- helpers -------------------------
__device__ __forceinline__ uint32_t smem_u32(const void* p) {
    uint32_t a;
    asm("{ .reg .u64 t; cvta.to.shared.u64 t, %1; cvt.u32.u64 %0, t; }" : "=r"(a) : "l"(p));
    return a;
}
__device__ __forceinline__ void cpasync16(uint32_t dst, const void* src) {
    asm volatile("cp.async.cg.shared.global [%0], [%1], 16;" :: "r"(dst), "l"(src) : "memory");
}
#define CP_COMMIT() asm volatile("cp.async.commit_group;" ::: "memory")
#define CP_WAIT(n)  asm volatile("cp.async.wait_group %0;" :: "n"(n) : "memory")

__device__ __forceinline__ void ldm_x4(uint32_t& r0, uint32_t& r1, uint32_t& r2, uint32_t& r3, uint32_t a) {
    asm volatile("ldmatrix.sync.aligned.m8n8.x4.shared.b16 {%0,%1,%2,%3}, [%4];"
                 : "=r"(r0), "=r"(r1), "=r"(r2), "=r"(r3) : "r"(a));
}
__device__ __forceinline__ void mma16816(float* d, const uint32_t* a, const uint32_t* b) {
    asm volatile(
        "mma.sync.aligned.m16n8k16.row.col.f32.bf16.bf16.f32 "
        "{%0,%1,%2,%3}, {%4,%5,%6,%7}, {%8,%9}, {%0,%1,%2,%3};"
        : "+f"(d[0]), "+f"(d[1]), "+f"(d[2]), "+f"(d[3])
        : "r"(a[0]), "r"(a[1]), "r"(a[2]), "r"(a[3]), "r"(b[0]), "r"(b[1]));
}
__device__ __forceinline__ uint32_t pack_bf16(__nv_bfloat16 a, __nv_bfloat16 b) {
    return ((uint32_t)__bfloat16_as_ushort(b) << 16) | __bfloat16_as_ushort(a);
}
__device__ __forceinline__ void split2(float v, __nv_bfloat16& h, __nv_bfloat16& l) {
    h = __float2bfloat16(v);
    l = __float2bfloat16(v - __bfloat162float(h));
}
// 64B-pitch XOR swizzle: row r, logical 16B segment ch (0..3) -> byte offset.
// 8 consecutive rows hit 8 distinct 16B slots mod 128B -> conflict-free ldmatrix/STS.
__device__ __forceinline__ uint32_t swz64(int r, int ch) {
    return (uint32_t)(r * 64 + ((ch ^ ((r >> 1) & 3)) << 4));
}

// ------------------------- fused prep kernel -------------------------
__global__ __launch_bounds__(256) void prep_all_kernel(
    const float* __restrict__ x,
    const float* __restrict__ Wq, const float* __restrict__ Wk,
    const float* __restrict__ Wv, const float* __restrict__ Wo)
{
    const int gb = blockIdx.x;
    if (gb < 8192) {
        int idx = gb * 256 + threadIdx.x;
        int m = idx >> 7;
        int k4 = (idx & 127) << 2;
        int nwin = m >> 9, s = m & 511;
        int b = nwin & 1, wb = (nwin >> 1) & 3, hb = nwin >> 3;
        int f = s >> 6, r = (s >> 3) & 7, cc = s & 7;
        const float* src = x + (size_t)((((b*8 + f)*32 + hb*8 + r)*32 + wb*8 + cc)) * CDIM + k4;
        float4 v = *(const float4*)src;
        __nv_bfloat16 h0,h1,h2,h3,l0,l1,l2,l3;
        split2(v.x,h0,l0); split2(v.y,h1,l1); split2(v.z,h2,l2); split2(v.w,h3,l3);
        uint2 hv = { pack_bf16(h0, h1), pack_bf16(h2, h3) };
        uint2 lv = { pack_bf16(l0, l1), pack_bf16(l2, l3) };
        *(uint2*)(g_xhi + (size_t)m * CDIM + k4) = hv;
        *(uint2*)(g_xlo + (size_t)m * CDIM + k4) = lv;
    } else if (gb < 12288) {
        int idx = (gb - 8192) * 256 + threadIdx.x;
        int n = idx & 511;
        int km = idx >> 9;
        int mat = km >> 9, k = km & 511;
        const float* W = (mat == 0) ? Wq : (mat == 1) ? Wk : (mat == 2) ? Wv : Wo;
        float v = W[(size_t)k * CDIM + n];
        __nv_bfloat16 h, l;
        split2(v, h, l);
        size_t dst = (size_t)(mat * 512 + n) * CDIM + k;
        g_Bhi[dst] = h;
        g_Blo[dst] = l;
    } else {
        int idx = (gb - 12288) * 256 + threadIdx.x;
        if (idx < 16 * SLEN) {
            int jj = idx >> 9, s = idx & 511;
            const float LN = 0.5756462732485114210f;    // ln(10000)/16
            float ang = (float)s * expf(-LN * (float)jj);
            float sn, cs;
            sincosf(ang, &sn, &cs);
            g_tabc[idx] = cs;
            g_tabs[idx] = sn;
        }
    }
}

// ------------------------- mma.sync GEMM (3-stage, BK=32, swizzled 64B rows) -------------------------
#define BM 128
#define BN 128
#define BK 32
#define PLSTG (128*64)        // 8192: one plane (128 rows x 64B)
#define STAGE (4*PLSTG)       // 32768: A(2pl)+B(2pl)
#define SA_OFF(st, pl) ((st)*STAGE + (pl)*PLSTG)
#define SB_OFF(st, pl) ((st)*STAGE + 2*PLSTG + (pl)*PLSTG)
#define SMEM_TOTAL (3*STAGE)  // 98304 -> 2 CTAs/SM

template<int MODE>
__global__ __launch_bounds__(256) void gemm_kernel(float* __restrict__ out,
                                                   const float* __restrict__ bo)
{
    extern __shared__ char smem[];
    const uint32_t sb = smem_u32(smem);
    const int tid  = threadIdx.x;
    const int lane = tid & 31;
    const int wid  = tid >> 5;
    const int warpM = wid >> 1;
    const int warpN = wid & 1;
    const int gid = lane >> 2;
    const int tig = lane & 3;
    const int lrow = lane & 15;
    const int lside = lane >> 4;

    const int m0 = blockIdx.y * BM;
    const int n0 = blockIdx.x * BN;
    const int nrow0 = MODE ? (1536 + n0) : n0;
    const __nv_bfloat16* Ah = MODE ? g_atthi : g_xhi;
    const __nv_bfloat16* Al = MODE ? g_attlo : g_xlo;

    float acc[2][8][4];
#pragma unroll
    for (int i = 0; i < 2; i++)
#pragma unroll
        for (int j = 0; j < 8; j++)
#pragma unroll
            for (int t = 0; t < 4; t++) acc[i][j][t] = 0.f;

    auto load_chunk = [&](int c, int st) {
        const int k0 = c * BK;
#pragma unroll
        for (int i = tid; i < 1024; i += 256) {       // A: 2pl x 128 rows x 4 segs
            int pl = i >> 9, rr = (i >> 2) & 127, ch = i & 3;
            const __nv_bfloat16* src = (pl ? Al : Ah) + (size_t)(m0 + rr) * CDIM + k0 + ch * 8;
            cpasync16(sb + SA_OFF(st, pl) + swz64(rr, ch), src);
        }
#pragma unroll
        for (int i = tid; i < 1024; i += 256) {       // B
            int pl = i >> 9, rr = (i >> 2) & 127, ch = i & 3;
            const __nv_bfloat16* src = (pl ? g_Blo : g_Bhi) + (size_t)(nrow0 + rr) * CDIM + k0 + ch * 8;
            cpasync16(sb + SB_OFF(st, pl) + swz64(rr, ch), src);
        }
        CP_COMMIT();
    };

    load_chunk(0, 0);
    load_chunk(1, 1);

    const int NCH = CDIM / BK;   // 16

    for (int c = 0; c < NCH; c++) {
        if (c == NCH - 1) CP_WAIT(0); else CP_WAIT(1);
        __syncthreads();
        if (c + 2 < NCH) load_chunk(c + 2, (c + 2) % 3);    // overwrites stage of chunk c-1: safe after barrier
        const int st = c % 3;
#pragma unroll
        for (int ks2 = 0; ks2 < 2; ks2++) {
            const int chq = ks2 * 2 + lside;                 // logical 16B segment 0..3
            uint32_t ah[2][4], al_[2][4];
#pragma unroll
            for (int mt = 0; mt < 2; mt++) {
                int ra = warpM*32 + mt*16 + lrow;
                ldm_x4(ah[mt][0], ah[mt][1], ah[mt][2], ah[mt][3],
                       sb + SA_OFF(st, 0) + swz64(ra, chq));
                ldm_x4(al_[mt][0], al_[mt][1], al_[mt][2], al_[mt][3],
                       sb + SA_OFF(st, 1) + swz64(ra, chq));
            }
            uint32_t bh[8][2], bl_[8][2];
#pragma unroll
            for (int ntp = 0; ntp < 4; ntp++) {
                int rb = warpN*64 + ntp*16 + lrow;
                ldm_x4(bh[2*ntp][0], bh[2*ntp+1][0], bh[2*ntp][1], bh[2*ntp+1][1],
                       sb + SB_OFF(st, 0) + swz64(rb, chq));
                ldm_x4(bl_[2*ntp][0], bl_[2*ntp+1][0], bl_[2*ntp][1], bl_[2*ntp+1][1],
                       sb + SB_OFF(st, 1) + swz64(rb, chq));
            }
#pragma unroll
            for (int mt = 0; mt < 2; mt++)
#pragma unroll
                for (int nt = 0; nt < 8; nt++) mma16816(acc[mt][nt], ah[mt], bh[nt]);
#pragma unroll
            for (int mt = 0; mt < 2; mt++)
#pragma unroll
                for (int nt = 0; nt < 8; nt++) mma16816(acc[mt][nt], al_[mt], bh[nt]);
#pragma unroll
            for (int mt = 0; mt < 2; mt++)
#pragma unroll
                for (int nt = 0; nt < 8; nt++) mma16816(acc[mt][nt], ah[mt], bl_[nt]);
        }
    }

    const int mwbase = m0 + warpM * 32;
    const int cwbase = n0 + warpN * 64;

#pragma unroll
    for (int mt = 0; mt < 2; mt++) {
#pragma unroll
        for (int nt = 0; nt < 8; nt++) {
            const int g = cwbase + nt * 8 + tig * 2;
            if (MODE == 0) {
                const int mat = g >> 9;
                const int cc = g & 511;
                const int head = cc >> 6;
                const int d = cc & 63;
#pragma unroll
                for (int half = 0; half < 2; half++) {
                    const int row = mwbase + mt * 16 + gid + half * 8;
                    const int nw = row >> 9;
                    const int s  = row & 511;
                    float v0 = acc[mt][nt][half * 2];
                    float v1 = acc[mt][nt][half * 2 + 1];
                    if (mat < 2 && d < 32) {
                        const int j0 = d >> 1;
                        float cs = g_tabc[j0 * 512 + s];
                        float sn = g_tabs[j0 * 512 + s];
                        float w0 = v0 * cs - v1 * sn;
                        float w1 = v1 * cs + v0 * sn;
                        v0 = w0; v1 = w1;
                    }
                    __nv_bfloat16 h0,h1,l0,l1;
                    split2(v0,h0,l0); split2(v1,h1,l1);
                    const int nhh = nw * NHEADS + head;
                    if (mat == 0) {
                        size_t base = ((size_t)nhh * SLEN + s) * DH + d;
                        *(uint32_t*)(g_Qh + base) = pack_bf16(h0, h1);
                        *(uint32_t*)(g_Ql + base) = pack_bf16(l0, l1);
                    } else if (mat == 1) {
                        size_t base = ((size_t)nhh * SLEN + s) * DH + d;
                        *(uint32_t*)(g_Kh + base) = pack_bf16(h0, h1);
                        *(uint32_t*)(g_Kl + base) = pack_bf16(l0, l1);
                    } else {
                        size_t vb = ((size_t)nhh * DH + d) * SLEN + s;
                        g_Vth[vb] = h0; g_Vth[vb + SLEN] = h1;
                        g_Vtl[vb] = l0; g_Vtl[vb + SLEN] = l1;
                    }
                }
            } else {
                const float2 bias = *(const float2*)(bo + g);
#pragma unroll
                for (int half = 0; half < 2; half++) {
                    const int row = mwbase + mt * 16 + gid + half * 8;
                    const int nwv = row >> 9, ss = row & 511;
                    const int b = nwv & 1, wb = (nwv >> 1) & 3, hb = nwv >> 3;
                    const int fr = ss >> 6, rr = (ss >> 3) & 7, c2 = ss & 7;
                    const size_t obase = ((size_t)b * (8*32*32) + (size_t)fr * (32*32)
                                        + (size_t)(hb*8 + rr) * 32 + (wb*8 + c2)) * CDIM;
                    float2 v = { acc[mt][nt][half*2] + bias.x,
                                 acc[mt][nt][half*2 + 1] + bias.y };
                    *(float2*)(out + obase + g) = v;
                }
            }
        }
    }
}

// ------------------------- tensor-core flash attention (3-stage KV, unchanged from R6) -------------------------
#define AP 144
#define QPL (128*AP)
#define KVSTG (4*64*AP)
#define SQ_OFF(pl)       ((pl) * QPL)
#define SK_OFF(st, pl)   (2*QPL + (st)*KVSTG + (pl)*(64*AP))
#define SV_OFF(st, pl)   (2*QPL + (st)*KVSTG + 2*(64*AP) + (pl)*(64*AP))
#define SP_OFF(pl)       (2*QPL + 3*KVSTG + (pl)*QPL)
#define ATTN_SMEM        (2*QPL + 3*KVSTG + 2*QPL)   // 184320

__global__ __launch_bounds__(256) void attn_kernel()
{
    extern __shared__ char smem[];
    const uint32_t sb = smem_u32(smem);
    const int qt = blockIdx.x;
    const int nh = blockIdx.y;
    const int tid = threadIdx.x;
    const int lane = tid & 31;
    const int wid = tid >> 5;
    const int gid = lane >> 2;
    const int tig = lane & 3;
    const int lrow = lane & 15;
    const int lside = lane >> 4;

    {
        const size_t qbase = ((size_t)nh * SLEN + qt * 128) * DH;
#pragma unroll
        for (int i = tid; i < 2048; i += 256) {
            int pl = i >> 10, r = (i >> 3) & 127, ch = i & 7;
            const __nv_bfloat16* src = (pl ? g_Ql : g_Qh) + qbase + (size_t)r * DH + ch * 8;
            cpasync16(sb + SQ_OFF(pl) + r * AP + ch * 16, src);
        }
        CP_COMMIT();
    }

    const int nkt = 2 * qt + 2;

    auto load_kv = [&](int kt, int st) {
#pragma unroll
        for (int i = tid; i < 2048; i += 256) {
            if (i < 1024) {
                int pl = i >> 9, r = (i >> 3) & 63, ch = i & 7;
                const __nv_bfloat16* src = (pl ? g_Kl : g_Kh)
                    + ((size_t)nh * SLEN + kt * 64 + r) * DH + ch * 8;
                cpasync16(sb + SK_OFF(st, pl) + r * AP + ch * 16, src);
            } else {
                int j = i - 1024;
                int pl = j >> 9, r = (j >> 3) & 63, ch = j & 7;
                const __nv_bfloat16* src = (pl ? g_Vtl : g_Vth)
                    + ((size_t)nh * DH + r) * SLEN + kt * 64 + ch * 8;
                cpasync16(sb + SV_OFF(st, pl) + r * AP + ch * 16, src);
            }
        }
        CP_COMMIT();
    };

    load_kv(0, 0);
    if (nkt > 1) load_kv(1, 1);

    float accO[8][4];
#pragma unroll
    for (int j = 0; j < 8; j++)
#pragma unroll
        for (int t = 0; t < 4; t++) accO[j][t] = 0.f;
    float lsum0 = 0.f, lsum1 = 0.f;

    const int qrow0 = qt * 128 + wid * 16;

    for (int kt = 0; kt < nkt; kt++) {
        if (kt == nkt - 1) CP_WAIT(0); else CP_WAIT(1);
        __syncthreads();
        if (kt + 2 < nkt) load_kv(kt + 2, (kt + 2) % 3);
        const int st = kt % 3;

        float accS[8][4];
#pragma unroll
        for (int j = 0; j < 8; j++)
#pragma unroll
            for (int t = 0; t < 4; t++) accS[j][t] = 0.f;

#pragma unroll
        for (int k4 = 0; k4 < 4; k4++) {
            const int kb = k4 * 32 + lside * 16;
            uint32_t qh[4], ql[4];
            ldm_x4(qh[0], qh[1], qh[2], qh[3], sb + SQ_OFF(0) + (wid*16 + lrow) * AP + kb);
            ldm_x4(ql[0], ql[1], ql[2], ql[3], sb + SQ_OFF(1) + (wid*16 + lrow) * AP + kb);
            uint32_t kh[8][2], kl_[8][2];
#pragma unroll
            for (int ntp = 0; ntp < 4; ntp++) {
                ldm_x4(kh[2*ntp][0], kh[2*ntp+1][0], kh[2*ntp][1], kh[2*ntp+1][1],
                       sb + SK_OFF(st, 0) + (ntp*16 + lrow) * AP + kb);
                ldm_x4(kl_[2*ntp][0], kl_[2*ntp+1][0], kl_[2*ntp][1], kl_[2*ntp+1][1],
                       sb + SK_OFF(st, 1) + (ntp*16 + lrow) * AP + kb);
            }
#pragma unroll
            for (int nt = 0; nt < 8; nt++) mma16816(accS[nt], qh, kh[nt]);
#pragma unroll
            for (int nt = 0; nt < 8; nt++) mma16816(accS[nt], ql, kh[nt]);
#pragma unroll
            for (int nt = 0; nt < 8; nt++) mma16816(accS[nt], qh, kl_[nt]);
        }

#pragma unroll
        for (int nt = 0; nt < 8; nt++) {
#pragma unroll
            for (int half = 0; half < 2; half++) {
                const int row = qrow0 + gid + half * 8;
                const int col0 = kt * 64 + nt * 8 + tig * 2;
                float s0 = accS[nt][half*2]     * 0.125f;
                float s1 = accS[nt][half*2 + 1] * 0.125f;
                float p0 = (col0     <= row) ? __expf(s0) : 0.f;
                float p1 = (col0 + 1 <= row) ? __expf(s1) : 0.f;
                if (half) lsum1 += p0 + p1; else lsum0 += p0 + p1;
                __nv_bfloat16 h0,h1,l0,l1;
                split2(p0,h0,l0); split2(p1,h1,l1);
                uint32_t off = (wid*16 + gid + half*8) * AP + (nt*8 + tig*2) * 2;
                *(uint32_t*)(smem + SP_OFF(0) + off) = pack_bf16(h0, h1);
                *(uint32_t*)(smem + SP_OFF(1) + off) = pack_bf16(l0, l1);
            }
        }
        __syncwarp();

#pragma unroll
        for (int k4 = 0; k4 < 4; k4++) {
            const int kb = k4 * 32 + lside * 16;
            uint32_t ph[4], pl_[4];
            ldm_x4(ph[0], ph[1], ph[2], ph[3], sb + SP_OFF(0) + (wid*16 + lrow) * AP + kb);
            ldm_x4(pl_[0], pl_[1], pl_[2], pl_[3], sb + SP_OFF(1) + (wid*16 + lrow) * AP + kb);
            uint32_t vh[8][2], vl_[8][2];
#pragma unroll
            for (int ntp = 0; ntp < 4; ntp++) {
                ldm_x4(vh[2*ntp][0], vh[2*ntp+1][0], vh[2*ntp][1], vh[2*ntp+1][1],
                       sb + SV_OFF(st, 0) + (ntp*16 + lrow) * AP + kb);
                ldm_x4(vl_[2*ntp][0], vl_[2*ntp+1][0], vl_[2*ntp][1], vl_[2*ntp+1][1],
                       sb + SV_OFF(st, 1) + (ntp*16 + lrow) * AP + kb);
            }
#pragma unroll
            for (int nt = 0; nt < 8; nt++) mma16816(accO[nt], ph,  vh[nt]);
#pragma unroll
            for (int nt = 0; nt < 8; nt++) mma16816(accO[nt], pl_, vh[nt]);
#pragma unroll
            for (int nt = 0; nt < 8; nt++) mma16816(accO[nt], ph,  vl_[nt]);
        }
    }

    lsum0 += __shfl_xor_sync(0xFFFFFFFF, lsum0, 1);
    lsum0 += __shfl_xor_sync(0xFFFFFFFF, lsum0, 2);
    lsum1 += __shfl_xor_sync(0xFFFFFFFF, lsum1, 1);
    lsum1 += __shfl_xor_sync(0xFFFFFFFF, lsum1, 2);
    const float inv0 = 1.f / lsum0;
    const float inv1 = 1.f / lsum1;

    const int nwn = nh >> 3, hh = nh & 7;
#pragma unroll
    for (int half = 0; half < 2; half++) {
        const int srow = qrow0 + gid + half * 8;
        const float inv = half ? inv1 : inv0;
        const size_t mrow = (size_t)nwn * SLEN + srow;
#pragma unroll
        for (int nt = 0; nt < 8; nt++) {
            const int d = nt * 8 + tig * 2;
            float v0 = accO[nt][half*2]     * inv;
            float v1 = accO[nt][half*2 + 1] * inv;
            __nv_bfloat16 h0,h1,l0,l1;
            split2(v0,h0,l0); split2(v1,h1,l1);
            size_t base = mrow * CDIM + hh * DH + d;
            *(uint32_t*)(g_atthi + base) = pack_bf16(h0, h1);
            *(uint32_t*)(g_attlo + base) = pack_bf16(l0, l1);
        }
    }
}

// ------------------------- launch -------------------------
extern "C" void kernel_launch(void* const* d_in, const int* in_sizes, int n_in,
                              void* d_out, int out_size)
{
    const float* x  = (const float*)d_in[0];
    const float* Wq = (const float*)d_in[1];
    const float* Wk = (const float*)d_in[2];
    const float* Wv = (const float*)d_in[3];
    const float* Wo = (const float*)d_in[4];
    const float* bo = (const float*)d_in[5];
    float* out = (float*)d_out;
    (void)in_sizes; (void)n_in; (void)out_size;

    static bool attr_done = false;
    if (!attr_done) {
        cudaFuncSetAttribute(gemm_kernel<0>, cudaFuncAttributeMaxDynamicSharedMemorySize, SMEM_TOTAL);
        cudaFuncSetAttribute(gemm_kernel<1>, cudaFuncAttributeMaxDynamicSharedMemorySize, SMEM_TOTAL);
        cudaFuncSetAttribute(attn_kernel, cudaFuncAttributeMaxDynamicSharedMemorySize, ATTN_SMEM);
        attr_done = true;
    }

    prep_all_kernel<<<12320, 256>>>(x, Wq, Wk, Wv, Wo);

    dim3 gq(12, MROWS / BM);             // N=1536
    gemm_kernel<0><<<gq, 256, SMEM_TOTAL>>>(nullptr, nullptr);

    dim3 ga(4, NWIN * NHEADS);
    attn_kernel<<<ga, 256, ATTN_SMEM>>>();

    dim3 go(4, MROWS / BM);              // N=512
    gemm_kernel<1><<<go, 256, SMEM_TOTAL>>>(out, bo);
}

// round 8
// speedup vs baseline: 1.6842x; 1.4442x over previous
#include <cuda_runtime.h>
#include <cuda_fp16.h>
#include <math.h>
#include <stdint.h>

#define CDIM   512
#define NHEADS 8
#define DH     64
#define NWIN   32
#define SLEN   512
#define MROWS  (NWIN*SLEN)   // 16384

// ------------------------- device scratch (no allocs) -------------------------
__device__ __align__(16) __half g_xh[MROWS*CDIM];
__device__ __align__(16) __half g_xl[MROWS*CDIM];
__device__ __align__(16) __half g_atth[MROWS*CDIM];
__device__ __align__(16) __half g_attl[MROWS*CDIM];
__device__ __align__(16) __half g_W[2048*CDIM];    // [n][k]: 0..1535 [Wq|Wk|Wv]^T, 1536..2047 Wo^T (fp16 hi only)
__device__ __align__(16) __half g_Qh[NWIN*NHEADS*SLEN*DH];
__device__ __align__(16) __half g_Ql[NWIN*NHEADS*SLEN*DH];
__device__ __align__(16) __half g_Kh[NWIN*NHEADS*SLEN*DH];   // hi only
__device__ __align__(16) __half g_Vt[NWIN*NHEADS*DH*SLEN];   // transposed [nh][d][t], hi only
__device__ float g_tabc[16*SLEN];
__device__ float g_tabs[16*SLEN];

// ------------------------- helpers -------------------------
__device__ __forceinline__ uint32_t smem_u32(const void* p) {
    uint32_t a;
    asm("{ .reg .u64 t; cvta.to.shared.u64 t, %1; cvt.u32.u64 %0, t; }" : "=r"(a) : "l"(p));
    return a;
}
__device__ __forceinline__ void cpasync16(uint32_t dst, const void* src) {
    asm volatile("cp.async.cg.shared.global [%0], [%1], 16;" :: "r"(dst), "l"(src) : "memory");
}
#define CP_COMMIT() asm volatile("cp.async.commit_group;" ::: "memory")
#define CP_WAIT(n)  asm volatile("cp.async.wait_group %0;" :: "n"(n) : "memory")

__device__ __forceinline__ void ldm_x4(uint32_t& r0, uint32_t& r1, uint32_t& r2, uint32_t& r3, uint32_t a) {
    asm volatile("ldmatrix.sync.aligned.m8n8.x4.shared.b16 {%0,%1,%2,%3}, [%4];"
                 : "=r"(r0), "=r"(r1), "=r"(r2), "=r"(r3) : "r"(a));
}
__device__ __forceinline__ void mma16816(float* d, const uint32_t* a, const uint32_t* b) {
    asm volatile(
        "mma.sync.aligned.m16n8k16.row.col.f32.f16.f16.f32 "
        "{%0,%1,%2,%3}, {%4,%5,%6,%7}, {%8,%9}, {%0,%1,%2,%3};"
        : "+f"(d[0]), "+f"(d[1]), "+f"(d[2]), "+f"(d[3])
        : "r"(a[0]), "r"(a[1]), "r"(a[2]), "r"(a[3]), "r"(b[0]), "r"(b[1]));
}
__device__ __forceinline__ uint32_t pack_h(__half a, __half b) {
    return ((uint32_t)__half_as_ushort(b) << 16) | __half_as_ushort(a);
}
__device__ __forceinline__ void split2h(float v, __half& h, __half& l) {
    h = __float2half_rn(v);
    l = __float2half_rn(v - __half2float(h));
}
// 64B-pitch XOR swizzle (BK=32 fp16 rows): conflict-free ldmatrix/STS
__device__ __forceinline__ uint32_t swz64(int r, int ch) {
    return (uint32_t)(r * 64 + ((ch ^ ((r >> 1) & 3)) << 4));
}
// 128B-pitch XOR swizzle (64-elem fp16 rows)
__device__ __forceinline__ uint32_t swz128(int r, int ch) {
    return (uint32_t)(r * 128 + ((ch ^ (r & 7)) << 4));
}

// ------------------------- fused prep kernel -------------------------
// blocks [0,8192): x gather+split(2pl); [8192,12288): W transpose (1pl); [12288,12320): rotary table
__global__ __launch_bounds__(256) void prep_all_kernel(
    const float* __restrict__ x,
    const float* __restrict__ Wq, const float* __restrict__ Wk,
    const float* __restrict__ Wv, const float* __restrict__ Wo)
{
    const int gb = blockIdx.x;
    if (gb < 8192) {
        int idx = gb * 256 + threadIdx.x;
        int m = idx >> 7;
        int k4 = (idx & 127) << 2;
        int nwin = m >> 9, s = m & 511;
        int b = nwin & 1, wb = (nwin >> 1) & 3, hb = nwin >> 3;
        int f = s >> 6, r = (s >> 3) & 7, cc = s & 7;
        const float* src = x + (size_t)((((b*8 + f)*32 + hb*8 + r)*32 + wb*8 + cc)) * CDIM + k4;
        float4 v = *(const float4*)src;
        __half h0,h1,h2,h3,l0,l1,l2,l3;
        split2h(v.x,h0,l0); split2h(v.y,h1,l1); split2h(v.z,h2,l2); split2h(v.w,h3,l3);
        uint2 hv = { pack_h(h0, h1), pack_h(h2, h3) };
        uint2 lv = { pack_h(l0, l1), pack_h(l2, l3) };
        *(uint2*)(g_xh + (size_t)m * CDIM + k4) = hv;
        *(uint2*)(g_xl + (size_t)m * CDIM + k4) = lv;
    } else if (gb < 12288) {
        int idx = (gb - 8192) * 256 + threadIdx.x;   // 2048*512
        int n = idx & 511;
        int km = idx >> 9;
        int mat = km >> 9, k = km & 511;
        const float* W = (mat == 0) ? Wq : (mat == 1) ? Wk : (mat == 2) ? Wv : Wo;
        float v = W[(size_t)k * CDIM + n];
        g_W[(size_t)(mat * 512 + n) * CDIM + k] = __float2half_rn(v);
    } else {
        int idx = (gb - 12288) * 256 + threadIdx.x;
        if (idx < 16 * SLEN) {
            int jj = idx >> 9, s = idx & 511;
            const float LN = 0.5756462732485114210f;    // ln(10000)/16
            float ang = (float)s * expf(-LN * (float)jj);
            float sn, cs;
            sincosf(ang, &sn, &cs);
            g_tabc[idx] = cs;
            g_tabs[idx] = sn;
        }
    }
}

// ------------------------- mma.sync GEMM (3-stage, BK=32, A 2-plane, B 1-plane) -------------------------
#define BM 128
#define BN 128
#define BK 32
#define PLSTG (128*64)        // 8192
#define STAGE (3*PLSTG)       // 24576: A(2pl)+B(1pl)
#define SA_OFF(st, pl) ((st)*STAGE + (pl)*PLSTG)
#define SB_OFF(st)     ((st)*STAGE + 2*PLSTG)
#define SMEM_TOTAL (3*STAGE)  // 73728 -> 2 CTAs/SM

template<int MODE>
__global__ __launch_bounds__(256) void gemm_kernel(float* __restrict__ out,
                                                   const float* __restrict__ bo)
{
    extern __shared__ char smem[];
    const uint32_t sb = smem_u32(smem);
    const int tid  = threadIdx.x;
    const int lane = tid & 31;
    const int wid  = tid >> 5;
    const int warpM = wid >> 1;
    const int warpN = wid & 1;
    const int gid = lane >> 2;
    const int tig = lane & 3;
    const int lrow = lane & 15;
    const int lside = lane >> 4;

    const int m0 = blockIdx.y * BM;
    const int n0 = blockIdx.x * BN;
    const int nrow0 = MODE ? (1536 + n0) : n0;
    const __half* Ah = MODE ? g_atth : g_xh;
    const __half* Al = MODE ? g_attl : g_xl;

    float acc[2][8][4];
#pragma unroll
    for (int i = 0; i < 2; i++)
#pragma unroll
        for (int j = 0; j < 8; j++)
#pragma unroll
            for (int t = 0; t < 4; t++) acc[i][j][t] = 0.f;

    auto load_chunk = [&](int c, int st) {
        const int k0 = c * BK;
#pragma unroll
        for (int i = tid; i < 1024; i += 256) {       // A: 2pl x 128 rows x 4 segs
            int pl = i >> 9, rr = (i >> 2) & 127, ch = i & 3;
            const __half* src = (pl ? Al : Ah) + (size_t)(m0 + rr) * CDIM + k0 + ch * 8;
            cpasync16(sb + SA_OFF(st, pl) + swz64(rr, ch), src);
        }
#pragma unroll
        for (int i = tid; i < 512; i += 256) {        // B: 1pl x 128 rows x 4 segs
            int rr = (i >> 2) & 127, ch = i & 3;
            const __half* src = g_W + (size_t)(nrow0 + rr) * CDIM + k0 + ch * 8;
            cpasync16(sb + SB_OFF(st) + swz64(rr, ch), src);
        }
        CP_COMMIT();
    };

    load_chunk(0, 0);
    load_chunk(1, 1);

    const int NCH = CDIM / BK;   // 16

    for (int c = 0; c < NCH; c++) {
        if (c == NCH - 1) CP_WAIT(0); else CP_WAIT(1);
        __syncthreads();
        if (c + 2 < NCH) load_chunk(c + 2, (c + 2) % 3);
        const int st = c % 3;
#pragma unroll
        for (int ks2 = 0; ks2 < 2; ks2++) {
            const int chq = ks2 * 2 + lside;
            uint32_t ah[2][4], al_[2][4];
#pragma unroll
            for (int mt = 0; mt < 2; mt++) {
                int ra = warpM*32 + mt*16 + lrow;
                ldm_x4(ah[mt][0], ah[mt][1], ah[mt][2], ah[mt][3],
                       sb + SA_OFF(st, 0) + swz64(ra, chq));
                ldm_x4(al_[mt][0], al_[mt][1], al_[mt][2], al_[mt][3],
                       sb + SA_OFF(st, 1) + swz64(ra, chq));
            }
            uint32_t bh[8][2];
#pragma unroll
            for (int ntp = 0; ntp < 4; ntp++) {
                int rb = warpN*64 + ntp*16 + lrow;
                ldm_x4(bh[2*ntp][0], bh[2*ntp+1][0], bh[2*ntp][1], bh[2*ntp+1][1],
                       sb + SB_OFF(st) + swz64(rb, chq));
            }
#pragma unroll
            for (int mt = 0; mt < 2; mt++)
#pragma unroll
                for (int nt = 0; nt < 8; nt++) mma16816(acc[mt][nt], ah[mt], bh[nt]);
#pragma unroll
            for (int mt = 0; mt < 2; mt++)
#pragma unroll
                for (int nt = 0; nt < 8; nt++) mma16816(acc[mt][nt], al_[mt], bh[nt]);
        }
    }

    const int mwbase = m0 + warpM * 32;
    const int cwbase = n0 + warpN * 64;

#pragma unroll
    for (int mt = 0; mt < 2; mt++) {
#pragma unroll
        for (int nt = 0; nt < 8; nt++) {
            const int g = cwbase + nt * 8 + tig * 2;
            if (MODE == 0) {
                const int mat = g >> 9;
                const int cc = g & 511;
                const int head = cc >> 6;
                const int d = cc & 63;
#pragma unroll
                for (int half = 0; half < 2; half++) {
                    const int row = mwbase + mt * 16 + gid + half * 8;
                    const int nw = row >> 9;
                    const int s  = row & 511;
                    float v0 = acc[mt][nt][half * 2];
                    float v1 = acc[mt][nt][half * 2 + 1];
                    if (mat < 2 && d < 32) {
                        const int j0 = d >> 1;
                        float cs = g_tabc[j0 * 512 + s];
                        float sn = g_tabs[j0 * 512 + s];
                        float w0 = v0 * cs - v1 * sn;
                        float w1 = v1 * cs + v0 * sn;
                        v0 = w0; v1 = w1;
                    }
                    const int nhh = nw * NHEADS + head;
                    if (mat == 0) {
                        __half h0,h1,l0,l1;
                        split2h(v0,h0,l0); split2h(v1,h1,l1);
                        size_t base = ((size_t)nhh * SLEN + s) * DH + d;
                        *(uint32_t*)(g_Qh + base) = pack_h(h0, h1);
                        *(uint32_t*)(g_Ql + base) = pack_h(l0, l1);
                    } else if (mat == 1) {
                        size_t base = ((size_t)nhh * SLEN + s) * DH + d;
                        *(uint32_t*)(g_Kh + base) = pack_h(__float2half_rn(v0), __float2half_rn(v1));
                    } else {
                        size_t vb = ((size_t)nhh * DH + d) * SLEN + s;
                        g_Vt[vb]        = __float2half_rn(v0);
                        g_Vt[vb + SLEN] = __float2half_rn(v1);
                    }
                }
            } else {
                const float2 bias = *(const float2*)(bo + g);
#pragma unroll
                for (int half = 0; half < 2; half++) {
                    const int row = mwbase + mt * 16 + gid + half * 8;
                    const int nwv = row >> 9, ss = row & 511;
                    const int b = nwv & 1, wb = (nwv >> 1) & 3, hb = nwv >> 3;
                    const int fr = ss >> 6, rr = (ss >> 3) & 7, c2 = ss & 7;
                    const size_t obase = ((size_t)b * (8*32*32) + (size_t)fr * (32*32)
                                        + (size_t)(hb*8 + rr) * 32 + (wb*8 + c2)) * CDIM;
                    float2 v = { acc[mt][nt][half*2] + bias.x,
                                 acc[mt][nt][half*2 + 1] + bias.y };
                    *(float2*)(out + obase + g) = v;
                }
            }
        }
    }
}

// ------------------------- flash attention (fp16, 2-MMA, 3-stage KV, swizzled) -------------------------
// smem: Q 2pl x 16KB | KV 3 stages x (K 8KB + V 8KB) | P 2pl x 16KB = 114688 -> 2 CTAs/SM
#define AQ_OFF(pl)   ((pl) * 16384)
#define AK_OFF(st)   (32768 + (st) * 16384)
#define AV_OFF(st)   (32768 + (st) * 16384 + 8192)
#define APP_OFF(pl)  (81920 + (pl) * 16384)
#define ATTN_SMEM    114688

__global__ __launch_bounds__(256) void attn_kernel()
{
    extern __shared__ char smem[];
    const uint32_t sb = smem_u32(smem);
    const int qt = blockIdx.x;
    const int nh = blockIdx.y;
    const int tid = threadIdx.x;
    const int lane = tid & 31;
    const int wid = tid >> 5;
    const int gid = lane >> 2;
    const int tig = lane & 3;
    const int lrow = lane & 15;
    const int lside = lane >> 4;

    // Q tile (128 x 64, 2 planes), swizzled 128B rows
    {
        const size_t qbase = ((size_t)nh * SLEN + qt * 128) * DH;
#pragma unroll
        for (int i = tid; i < 2048; i += 256) {
            int pl = i >> 10, r = (i >> 3) & 127, ch = i & 7;
            const __half* src = (pl ? g_Ql : g_Qh) + qbase + (size_t)r * DH + ch * 8;
            cpasync16(sb + AQ_OFF(pl) + swz128(r, ch), src);
        }
        CP_COMMIT();
    }

    const int nkt = 2 * qt + 2;

    auto load_kv = [&](int kt, int st) {
#pragma unroll
        for (int i = tid; i < 1024; i += 256) {
            if (i < 512) {                        // K tile [t][d], hi only
                int r = (i >> 3) & 63, ch = i & 7;
                const __half* src = g_Kh + ((size_t)nh * SLEN + kt * 64 + r) * DH + ch * 8;
                cpasync16(sb + AK_OFF(st) + swz128(r, ch), src);
            } else {                              // V^T tile [d][t], hi only
                int j = i - 512;
                int r = (j >> 3) & 63, ch = j & 7;
                const __half* src = g_Vt + ((size_t)nh * DH + r) * SLEN + kt * 64 + ch * 8;
                cpasync16(sb + AV_OFF(st) + swz128(r, ch), src);
            }
        }
        CP_COMMIT();
    };

    load_kv(0, 0);
    if (nkt > 1) load_kv(1, 1);

    float accO[8][4];
#pragma unroll
    for (int j = 0; j < 8; j++)
#pragma unroll
        for (int t = 0; t < 4; t++) accO[j][t] = 0.f;
    float lsum0 = 0.f, lsum1 = 0.f;

    const int qrow0 = qt * 128 + wid * 16;

    for (int kt = 0; kt < nkt; kt++) {
        if (kt == nkt - 1) CP_WAIT(0); else CP_WAIT(1);
        __syncthreads();
        if (kt + 2 < nkt) load_kv(kt + 2, (kt + 2) % 3);
        const int st = kt % 3;

        // ---- S = Q K^T (2 planes) ----
        float accS[8][4];
#pragma unroll
        for (int j = 0; j < 8; j++)
#pragma unroll
            for (int t = 0; t < 4; t++) accS[j][t] = 0.f;

#pragma unroll
        for (int k4 = 0; k4 < 4; k4++) {
            const int chq = k4 * 2 + lside;
            uint32_t qh[4], ql[4];
            ldm_x4(qh[0], qh[1], qh[2], qh[3], sb + AQ_OFF(0) + swz128(wid*16 + lrow, chq));
            ldm_x4(ql[0], ql[1], ql[2], ql[3], sb + AQ_OFF(1) + swz128(wid*16 + lrow, chq));
            uint32_t kh[8][2];
#pragma unroll
            for (int ntp = 0; ntp < 4; ntp++) {
                ldm_x4(kh[2*ntp][0], kh[2*ntp+1][0], kh[2*ntp][1], kh[2*ntp+1][1],
                       sb + AK_OFF(st) + swz128(ntp*16 + lrow, chq));
            }
#pragma unroll
            for (int nt = 0; nt < 8; nt++) mma16816(accS[nt], qh, kh[nt]);
#pragma unroll
            for (int nt = 0; nt < 8; nt++) mma16816(accS[nt], ql, kh[nt]);
        }

        // ---- exp + causal + l + fp16-split P (warp-private rows, swizzled) ----
#pragma unroll
        for (int nt = 0; nt < 8; nt++) {
#pragma unroll
            for (int half = 0; half < 2; half++) {
                const int row = qrow0 + gid + half * 8;
                const int col0 = kt * 64 + nt * 8 + tig * 2;
                float s0 = accS[nt][half*2]     * 0.125f;
                float s1 = accS[nt][half*2 + 1] * 0.125f;
                float p0 = (col0     <= row) ? __expf(s0) : 0.f;
                float p1 = (col0 + 1 <= row) ? __expf(s1) : 0.f;
                if (half) lsum1 += p0 + p1; else lsum0 += p0 + p1;
                __half h0,h1,l0,l1;
                split2h(p0,h0,l0); split2h(p1,h1,l1);
                const int r = wid*16 + gid + half*8;
                uint32_t off = (uint32_t)(r * 128 + ((nt ^ (r & 7)) << 4) + tig * 4);
                *(uint32_t*)(smem + APP_OFF(0) + off) = pack_h(h0, h1);
                *(uint32_t*)(smem + APP_OFF(1) + off) = pack_h(l0, l1);
            }
        }
        __syncwarp();

        // ---- O += P V (2 planes) ----
#pragma unroll
        for (int k4 = 0; k4 < 4; k4++) {
            const int chq = k4 * 2 + lside;
            uint32_t ph[4], pl_[4];
            ldm_x4(ph[0], ph[1], ph[2], ph[3], sb + APP_OFF(0) + swz128(wid*16 + lrow, chq));
            ldm_x4(pl_[0], pl_[1], pl_[2], pl_[3], sb + APP_OFF(1) + swz128(wid*16 + lrow, chq));
            uint32_t vh[8][2];
#pragma unroll
            for (int ntp = 0; ntp < 4; ntp++) {
                ldm_x4(vh[2*ntp][0], vh[2*ntp+1][0], vh[2*ntp][1], vh[2*ntp+1][1],
                       sb + AV_OFF(st) + swz128(ntp*16 + lrow, chq));
            }
#pragma unroll
            for (int nt = 0; nt < 8; nt++) mma16816(accO[nt], ph,  vh[nt]);
#pragma unroll
            for (int nt = 0; nt < 8; nt++) mma16816(accO[nt], pl_, vh[nt]);
        }
    }

    // ---- finalize ----
    lsum0 += __shfl_xor_sync(0xFFFFFFFF, lsum0, 1);
    lsum0 += __shfl_xor_sync(0xFFFFFFFF, lsum0, 2);
    lsum1 += __shfl_xor_sync(0xFFFFFFFF, lsum1, 1);
    lsum1 += __shfl_xor_sync(0xFFFFFFFF, lsum1, 2);
    const float inv0 = 1.f / lsum0;
    const float inv1 = 1.f / lsum1;

    const int nwn = nh >> 3, hh = nh & 7;
#pragma unroll
    for (int half = 0; half < 2; half++) {
        const int srow = qrow0 + gid + half * 8;
        const float inv = half ? inv1 : inv0;
        const size_t mrow = (size_t)nwn * SLEN + srow;
#pragma unroll
        for (int nt = 0; nt < 8; nt++) {
            const int d = nt * 8 + tig * 2;
            float v0 = accO[nt][half*2]     * inv;
            float v1 = accO[nt][half*2 + 1] * inv;
            __half h0,h1,l0,l1;
            split2h(v0,h0,l0); split2h(v1,h1,l1);
            size_t base = mrow * CDIM + hh * DH + d;
            *(uint32_t*)(g_atth + base) = pack_h(h0, h1);
            *(uint32_t*)(g_attl + base) = pack_h(l0, l1);
        }
    }
}

// ------------------------- launch -------------------------
extern "C" void kernel_launch(void* const* d_in, const int* in_sizes, int n_in,
                              void* d_out, int out_size)
{
    const float* x  = (const float*)d_in[0];
    const float* Wq = (const float*)d_in[1];
    const float* Wk = (const float*)d_in[2];
    const float* Wv = (const float*)d_in[3];
    const float* Wo = (const float*)d_in[4];
    const float* bo = (const float*)d_in[5];
    float* out = (float*)d_out;
    (void)in_sizes; (void)n_in; (void)out_size;

    static bool attr_done = false;
    if (!attr_done) {
        cudaFuncSetAttribute(gemm_kernel<0>, cudaFuncAttributeMaxDynamicSharedMemorySize, SMEM_TOTAL);
        cudaFuncSetAttribute(gemm_kernel<1>, cudaFuncAttributeMaxDynamicSharedMemorySize, SMEM_TOTAL);
        cudaFuncSetAttribute(attn_kernel, cudaFuncAttributeMaxDynamicSharedMemorySize, ATTN_SMEM);
        attr_done = true;
    }

    prep_all_kernel<<<12320, 256>>>(x, Wq, Wk, Wv, Wo);

    dim3 gq(12, MROWS / BM);             // N=1536
    gemm_kernel<0><<<gq, 256, SMEM_TOTAL>>>(nullptr, nullptr);

    dim3 ga(4, NWIN * NHEADS);
    attn_kernel<<<ga, 256, ATTN_SMEM>>>();

    dim3 go(4, MROWS / BM);              // N=512
    gemm_kernel<1><<<go, 256, SMEM_TOTAL>>>(out, bo);
}

// round 10
// speedup vs baseline: 2.1986x; 1.3055x over previous
#include <cuda_runtime.h>
#include <cuda_fp16.h>
#include <math.h>
#include <stdint.h>

#define CDIM   512
#define NHEADS 8
#define DH     64
#define NWIN   32
#define SLEN   512
#define MROWS  (NWIN*SLEN)   // 16384

// ------------------------- device scratch (no allocs) -------------------------
__device__ __align__(16) __half g_xh[MROWS*CDIM];          // gathered x, fp16
__device__ __align__(16) __half g_atth[MROWS*CDIM];        // attention out, fp16
__device__ __align__(16) __half g_W[2048*CDIM];            // [n][k]: 0..1535 [Wq|Wk|Wv]^T, 1536..2047 Wo^T
__device__ __align__(16) __half g_Qh[NWIN*NHEADS*SLEN*DH]; // Q split 2-plane (score accuracy)
__device__ __align__(16) __half g_Ql[NWIN*NHEADS*SLEN*DH];
__device__ __align__(16) __half g_Kh[NWIN*NHEADS*SLEN*DH]; // hi only
__device__ __align__(16) __half g_Vt[NWIN*NHEADS*DH*SLEN]; // transposed [nh][d][t], hi only
__device__ float g_tabc[16*SLEN];
__device__ float g_tabs[16*SLEN];

// ------------------------- helpers -------------------------
__device__ __forceinline__ uint32_t smem_u32(const void* p) {
    uint32_t a;
    asm("{ .reg .u64 t; cvta.to.shared.u64 t, %1; cvt.u32.u64 %0, t; }" : "=r"(a) : "l"(p));
    return a;
}
__device__ __forceinline__ void cpasync16(uint32_t dst, const void* src) {
    asm volatile("cp.async.cg.shared.global [%0], [%1], 16;" :: "r"(dst), "l"(src) : "memory");
}
#define CP_COMMIT() asm volatile("cp.async.commit_group;" ::: "memory")
#define CP_WAIT(n)  asm volatile("cp.async.wait_group %0;" :: "n"(n) : "memory")

__device__ __forceinline__ void ldm_x4(uint32_t& r0, uint32_t& r1, uint32_t& r2, uint32_t& r3, uint32_t a) {
    asm volatile("ldmatrix.sync.aligned.m8n8.x4.shared.b16 {%0,%1,%2,%3}, [%4];"
                 : "=r"(r0), "=r"(r1), "=r"(r2), "=r"(r3) : "r"(a));
}
__device__ __forceinline__ void mma16816(float* d, const uint32_t* a, const uint32_t* b) {
    asm volatile(
        "mma.sync.aligned.m16n8k16.row.col.f32.f16.f16.f32 "
        "{%0,%1,%2,%3}, {%4,%5,%6,%7}, {%8,%9}, {%0,%1,%2,%3};"
        : "+f"(d[0]), "+f"(d[1]), "+f"(d[2]), "+f"(d[3])
        : "r"(a[0]), "r"(a[1]), "r"(a[2]), "r"(a[3]), "r"(b[0]), "r"(b[1]));
}
__device__ __forceinline__ uint32_t pack_h(__half a, __half b) {
    return ((uint32_t)__half_as_ushort(b) << 16) | __half_as_ushort(a);
}
__device__ __forceinline__ void split2h(float v, __half& h, __half& l) {
    h = __float2half_rn(v);
    l = __float2half_rn(v - __half2float(h));
}
// 64B-pitch XOR swizzle (BK=32 fp16 rows): conflict-free ldmatrix/STS
__device__ __forceinline__ uint32_t swz64(int r, int ch) {
    return (uint32_t)(r * 64 + ((ch ^ ((r >> 1) & 3)) << 4));
}
// 128B-pitch XOR swizzle (64-elem fp16 rows)
__device__ __forceinline__ uint32_t swz128(int r, int ch) {
    return (uint32_t)(r * 128 + ((ch ^ (r & 7)) << 4));
}

// ------------------------- fused prep kernel -------------------------
// blocks [0,4096): x gather->fp16 (2 float4 per thread); [4096,8192): W transpose; [8192,8224): rotary table
__global__ __launch_bounds__(256) void prep_all_kernel(
    const float* __restrict__ x,
    const float* __restrict__ Wq, const float* __restrict__ Wk,
    const float* __restrict__ Wv, const float* __restrict__ Wo)
{
    const int gb = blockIdx.x;
    if (gb < 4096) {
        // 16384*512 elems = 2,097,152 float4s; 4096 blocks * 256 thr * 2 = 2,097,152
        int t2 = (gb * 256 + threadIdx.x) * 2;
#pragma unroll
        for (int u = 0; u < 2; u++) {
            int id4 = t2 + u;
            int m = id4 >> 7;
            int k4 = (id4 & 127) << 2;
            int nwin = m >> 9, s = m & 511;
            int b = nwin & 1, wb = (nwin >> 1) & 3, hb = nwin >> 3;
            int f = s >> 6, r = (s >> 3) & 7, cc = s & 7;
            const float* src = x + (size_t)((((b*8 + f)*32 + hb*8 + r)*32 + wb*8 + cc)) * CDIM + k4;
            float4 v = *(const float4*)src;
            uint2 hv = { pack_h(__float2half_rn(v.x), __float2half_rn(v.y)),
                         pack_h(__float2half_rn(v.z), __float2half_rn(v.w)) };
            *(uint2*)(g_xh + (size_t)m * CDIM + k4) = hv;
        }
    } else if (gb < 8192) {
        int idx = (gb - 4096) * 256 + threadIdx.x;     // 2048*512 elems
        int n = idx & 511;
        int km = idx >> 9;
        int mat = km >> 9, k = km & 511;
        const float* W = (mat == 0) ? Wq : (mat == 1) ? Wk : (mat == 2) ? Wv : Wo;
        float v = W[(size_t)k * CDIM + n];
        g_W[(size_t)(mat * 512 + n) * CDIM + k] = __float2half_rn(v);
    } else {
        int idx = (gb - 8192) * 256 + threadIdx.x;
        if (idx < 16 * SLEN) {
            int jj = idx >> 9, s = idx & 511;
            const float LN = 0.5756462732485114210f;    // ln(10000)/16
            float ang = (float)s * expf(-LN * (float)jj);
            float sn, cs;
            sincosf(ang, &sn, &cs);
            g_tabc[idx] = cs;
            g_tabs[idx] = sn;
        }
    }
}

// ------------------------- mma.sync GEMM (3-stage, BK=32, A 1-plane, B 1-plane) -------------------------
#define BM 128
#define BN 128
#define BK 32
#define PLSTG (128*64)        // 8192
#define STAGE (2*PLSTG)       // 16384: A + B
#define SA_OFF(st)  ((st)*STAGE)
#define SB_OFF(st)  ((st)*STAGE + PLSTG)
#define SMEM_TOTAL (3*STAGE)  // 49152

template<int MODE>
__global__ __launch_bounds__(256) void gemm_kernel(float* __restrict__ out,
                                                   const float* __restrict__ bo)
{
    extern __shared__ char smem[];
    const uint32_t sb = smem_u32(smem);
    const int tid  = threadIdx.x;
    const int lane = tid & 31;
    const int wid  = tid >> 5;
    const int warpM = wid >> 1;
    const int warpN = wid & 1;
    const int gid = lane >> 2;
    const int tig = lane & 3;
    const int lrow = lane & 15;
    const int lside = lane >> 4;

    const int m0 = blockIdx.y * BM;
    const int n0 = blockIdx.x * BN;
    const int nrow0 = MODE ? (1536 + n0) : n0;
    const __half* Ap = MODE ? g_atth : g_xh;

    float acc[2][8][4];
#pragma unroll
    for (int i = 0; i < 2; i++)
#pragma unroll
        for (int j = 0; j < 8; j++)
#pragma unroll
            for (int t = 0; t < 4; t++) acc[i][j][t] = 0.f;

    auto load_chunk = [&](int c, int st) {
        const int k0 = c * BK;
#pragma unroll
        for (int i = tid; i < 512; i += 256) {        // A: 128 rows x 4 segs
            int rr = (i >> 2) & 127, ch = i & 3;
            const __half* src = Ap + (size_t)(m0 + rr) * CDIM + k0 + ch * 8;
            cpasync16(sb + SA_OFF(st) + swz64(rr, ch), src);
        }
#pragma unroll
        for (int i = tid; i < 512; i += 256) {        // B: 128 rows x 4 segs
            int rr = (i >> 2) & 127, ch = i & 3;
            const __half* src = g_W + (size_t)(nrow0 + rr) * CDIM + k0 + ch * 8;
            cpasync16(sb + SB_OFF(st) + swz64(rr, ch), src);
        }
        CP_COMMIT();
    };

    load_chunk(0, 0);
    load_chunk(1, 1);

    const int NCH = CDIM / BK;   // 16

    for (int c = 0; c < NCH; c++) {
        if (c == NCH - 1) CP_WAIT(0); else CP_WAIT(1);
        __syncthreads();
        if (c + 2 < NCH) load_chunk(c + 2, (c + 2) % 3);
        const int st = c % 3;
#pragma unroll
        for (int ks2 = 0; ks2 < 2; ks2++) {
            const int chq = ks2 * 2 + lside;
            uint32_t ah[2][4];
#pragma unroll
            for (int mt = 0; mt < 2; mt++) {
                int ra = warpM*32 + mt*16 + lrow;
                ldm_x4(ah[mt][0], ah[mt][1], ah[mt][2], ah[mt][3],
                       sb + SA_OFF(st) + swz64(ra, chq));
            }
            uint32_t bh[8][2];
#pragma unroll
            for (int ntp = 0; ntp < 4; ntp++) {
                int rb = warpN*64 + ntp*16 + lrow;
                ldm_x4(bh[2*ntp][0], bh[2*ntp+1][0], bh[2*ntp][1], bh[2*ntp+1][1],
                       sb + SB_OFF(st) + swz64(rb, chq));
            }
#pragma unroll
            for (int mt = 0; mt < 2; mt++)
#pragma unroll
                for (int nt = 0; nt < 8; nt++) mma16816(acc[mt][nt], ah[mt], bh[nt]);
        }
    }

    const int mwbase = m0 + warpM * 32;
    const int cwbase = n0 + warpN * 64;

#pragma unroll
    for (int mt = 0; mt < 2; mt++) {
#pragma unroll
        for (int nt = 0; nt < 8; nt++) {
            const int g = cwbase + nt * 8 + tig * 2;
            if (MODE == 0) {
                const int mat = g >> 9;
                const int cc = g & 511;
                const int head = cc >> 6;
                const int d = cc & 63;
#pragma unroll
                for (int half = 0; half < 2; half++) {
                    const int row = mwbase + mt * 16 + gid + half * 8;
                    const int nw = row >> 9;
                    const int s  = row & 511;
                    float v0 = acc[mt][nt][half * 2];
                    float v1 = acc[mt][nt][half * 2 + 1];
                    if (mat < 2 && d < 32) {
                        const int j0 = d >> 1;
                        float cs = g_tabc[j0 * 512 + s];
                        float sn = g_tabs[j0 * 512 + s];
                        float w0 = v0 * cs - v1 * sn;
                        float w1 = v1 * cs + v0 * sn;
                        v0 = w0; v1 = w1;
                    }
                    const int nhh = nw * NHEADS + head;
                    if (mat == 0) {
                        __half h0,h1,l0,l1;
                        split2h(v0,h0,l0); split2h(v1,h1,l1);
                        size_t base = ((size_t)nhh * SLEN + s) * DH + d;
                        *(uint32_t*)(g_Qh + base) = pack_h(h0, h1);
                        *(uint32_t*)(g_Ql + base) = pack_h(l0, l1);
                    } else if (mat == 1) {
                        size_t base = ((size_t)nhh * SLEN + s) * DH + d;
                        *(uint32_t*)(g_Kh + base) = pack_h(__float2half_rn(v0), __float2half_rn(v1));
                    } else {
                        size_t vb = ((size_t)nhh * DH + d) * SLEN + s;
                        g_Vt[vb]        = __float2half_rn(v0);
                        g_Vt[vb + SLEN] = __float2half_rn(v1);
                    }
                }
            } else {
                const float2 bias = *(const float2*)(bo + g);
#pragma unroll
                for (int half = 0; half < 2; half++) {
                    const int row = mwbase + mt * 16 + gid + half * 8;
                    const int nwv = row >> 9, ss = row & 511;
                    const int b = nwv & 1, wb = (nwv >> 1) & 3, hb = nwv >> 3;
                    const int fr = ss >> 6, rr = (ss >> 3) & 7, c2 = ss & 7;
                    const size_t obase = ((size_t)b * (8*32*32) + (size_t)fr * (32*32)
                                        + (size_t)(hb*8 + rr) * 32 + (wb*8 + c2)) * CDIM;
                    float2 v = { acc[mt][nt][half*2] + bias.x,
                                 acc[mt][nt][half*2 + 1] + bias.y };
                    *(float2*)(out + obase + g) = v;
                }
            }
        }
    }
}

// ------------------------- flash attention (fp16, Q/P 2-plane, K/V 1-plane) -------------------------
// smem: Q 2pl x 16KB | KV 3 stages x (K 8KB + V 8KB) | P 2pl x 16KB = 114688 -> 2 CTAs/SM
#define AQ_OFF(pl)   ((pl) * 16384)
#define AK_OFF(st)   (32768 + (st) * 16384)
#define AV_OFF(st)   (32768 + (st) * 16384 + 8192)
#define APP_OFF(pl)  (81920 + (pl) * 16384)
#define ATTN_SMEM    114688

__global__ __launch_bounds__(256) void attn_kernel()
{
    extern __shared__ char smem[];
    const uint32_t sb = smem_u32(smem);
    const int qt = blockIdx.x;
    const int nh = blockIdx.y;
    const int tid = threadIdx.x;
    const int lane = tid & 31;
    const int wid = tid >> 5;
    const int gid = lane >> 2;
    const int tig = lane & 3;
    const int lrow = lane & 15;
    const int lside = lane >> 4;

    // Q tile (128 x 64, 2 planes), swizzled 128B rows
    {
        const size_t qbase = ((size_t)nh * SLEN + qt * 128) * DH;
#pragma unroll
        for (int i = tid; i < 2048; i += 256) {
            int pl = i >> 10, r = (i >> 3) & 127, ch = i & 7;
            const __half* src = (pl ? g_Ql : g_Qh) + qbase + (size_t)r * DH + ch * 8;
            cpasync16(sb + AQ_OFF(pl) + swz128(r, ch), src);
        }
        CP_COMMIT();
    }

    const int nkt = 2 * qt + 2;

    auto load_kv = [&](int kt, int st) {
#pragma unroll
        for (int i = tid; i < 1024; i += 256) {
            if (i < 512) {                        // K tile [t][d], hi only
                int r = (i >> 3) & 63, ch = i & 7;
                const __half* src = g_Kh + ((size_t)nh * SLEN + kt * 64 + r) * DH + ch * 8;
                cpasync16(sb + AK_OFF(st) + swz128(r, ch), src);
            } else {                              // V^T tile [d][t], hi only
                int j = i - 512;
                int r = (j >> 3) & 63, ch = j & 7;
                const __half* src = g_Vt + ((size_t)nh * DH + r) * SLEN + kt * 64 + ch * 8;
                cpasync16(sb + AV_OFF(st) + swz128(r, ch), src);
            }
        }
        CP_COMMIT();
    };

    load_kv(0, 0);
    if (nkt > 1) load_kv(1, 1);

    float accO[8][4];
#pragma unroll
    for (int j = 0; j < 8; j++)
#pragma unroll
        for (int t = 0; t < 4; t++) accO[j][t] = 0.f;
    float lsum0 = 0.f, lsum1 = 0.f;

    const int qrow0 = qt * 128 + wid * 16;

    for (int kt = 0; kt < nkt; kt++) {
        if (kt == nkt - 1) CP_WAIT(0); else CP_WAIT(1);
        __syncthreads();
        if (kt + 2 < nkt) load_kv(kt + 2, (kt + 2) % 3);
        const int st = kt % 3;

        // ---- S = Q K^T (2 planes on Q) ----
        float accS[8][4];
#pragma unroll
        for (int j = 0; j < 8; j++)
#pragma unroll
            for (int t = 0; t < 4; t++) accS[j][t] = 0.f;

#pragma unroll
        for (int k4 = 0; k4 < 4; k4++) {
            const int chq = k4 * 2 + lside;
            uint32_t qh[4], ql[4];
            ldm_x4(qh[0], qh[1], qh[2], qh[3], sb + AQ_OFF(0) + swz128(wid*16 + lrow, chq));
            ldm_x4(ql[0], ql[1], ql[2], ql[3], sb + AQ_OFF(1) + swz128(wid*16 + lrow, chq));
            uint32_t kh[8][2];
#pragma unroll
            for (int ntp = 0; ntp < 4; ntp++) {
                ldm_x4(kh[2*ntp][0], kh[2*ntp+1][0], kh[2*ntp][1], kh[2*ntp+1][1],
                       sb + AK_OFF(st) + swz128(ntp*16 + lrow, chq));
            }
#pragma unroll
            for (int nt = 0; nt < 8; nt++) mma16816(accS[nt], qh, kh[nt]);
#pragma unroll
            for (int nt = 0; nt < 8; nt++) mma16816(accS[nt], ql, kh[nt]);
        }

        // ---- exp + causal + l + fp16-split P (warp-private rows, swizzled) ----
#pragma unroll
        for (int nt = 0; nt < 8; nt++) {
#pragma unroll
            for (int half = 0; half < 2; half++) {
                const int row = qrow0 + gid + half * 8;
                const int col0 = kt * 64 + nt * 8 + tig * 2;
                float s0 = accS[nt][half*2]     * 0.125f;
                float s1 = accS[nt][half*2 + 1] * 0.125f;
                float p0 = (col0     <= row) ? __expf(s0) : 0.f;
                float p1 = (col0 + 1 <= row) ? __expf(s1) : 0.f;
                if (half) lsum1 += p0 + p1; else lsum0 += p0 + p1;
                __half h0,h1,l0,l1;
                split2h(p0,h0,l0); split2h(p1,h1,l1);
                const int r = wid*16 + gid + half*8;
                uint32_t off = (uint32_t)(r * 128 + ((nt ^ (r & 7)) << 4) + tig * 4);
                *(uint32_t*)(smem + APP_OFF(0) + off) = pack_h(h0, h1);
                *(uint32_t*)(smem + APP_OFF(1) + off) = pack_h(l0, l1);
            }
        }
        __syncwarp();

        // ---- O += P V (2 planes on P) ----
#pragma unroll
        for (int k4 = 0; k4 < 4; k4++) {
            const int chq = k4 * 2 + lside;
            uint32_t ph[4], pl_[4];
            ldm_x4(ph[0], ph[1], ph[2], ph[3], sb + APP_OFF(0) + swz128(wid*16 + lrow, chq));
            ldm_x4(pl_[0], pl_[1], pl_[2], pl_[3], sb + APP_OFF(1) + swz128(wid*16 + lrow, chq));
            uint32_t vh[8][2];
#pragma unroll
            for (int ntp = 0; ntp < 4; ntp++) {
                ldm_x4(vh[2*ntp][0], vh[2*ntp+1][0], vh[2*ntp][1], vh[2*ntp+1][1],
                       sb + AV_OFF(st) + swz128(ntp*16 + lrow, chq));
            }
#pragma unroll
            for (int nt = 0; nt < 8; nt++) mma16816(accO[nt], ph,  vh[nt]);
#pragma unroll
            for (int nt = 0; nt < 8; nt++) mma16816(accO[nt], pl_, vh[nt]);
        }
    }

    // ---- finalize: write att hi plane only ----
    lsum0 += __shfl_xor_sync(0xFFFFFFFF, lsum0, 1);
    lsum0 += __shfl_xor_sync(0xFFFFFFFF, lsum0, 2);
    lsum1 += __shfl_xor_sync(0xFFFFFFFF, lsum1, 1);
    lsum1 += __shfl_xor_sync(0xFFFFFFFF, lsum1, 2);
    const float inv0 = 1.f / lsum0;
    const float inv1 = 1.f / lsum1;

    const int nwn = nh >> 3, hh = nh & 7;
#pragma unroll
    for (int half = 0; half < 2; half++) {
        const int srow = qrow0 + gid + half * 8;
        const float inv = half ? inv1 : inv0;
        const size_t mrow = (size_t)nwn * SLEN + srow;
#pragma unroll
        for (int nt = 0; nt < 8; nt++) {
            const int d = nt * 8 + tig * 2;
            float v0 = accO[nt][half*2]     * inv;
            float v1 = accO[nt][half*2 + 1] * inv;
            size_t base = mrow * CDIM + hh * DH + d;
            *(uint32_t*)(g_atth + base) = pack_h(__float2half_rn(v0), __float2half_rn(v1));
        }
    }
}

// ------------------------- launch -------------------------
extern "C" void kernel_launch(void* const* d_in, const int* in_sizes, int n_in,
                              void* d_out, int out_size)
{
    const float* x  = (const float*)d_in[0];
    const float* Wq = (const float*)d_in[1];
    const float* Wk = (const float*)d_in[2];
    const float* Wv = (const float*)d_in[3];
    const float* Wo = (const float*)d_in[4];
    const float* bo = (const float*)d_in[5];
    float* out = (float*)d_out;
    (void)in_sizes; (void)n_in; (void)out_size;

    static bool attr_done = false;
    if (!attr_done) {
        cudaFuncSetAttribute(gemm_kernel<0>, cudaFuncAttributeMaxDynamicSharedMemorySize, SMEM_TOTAL);
        cudaFuncSetAttribute(gemm_kernel<1>, cudaFuncAttributeMaxDynamicSharedMemorySize, SMEM_TOTAL);
        cudaFuncSetAttribute(attn_kernel, cudaFuncAttributeMaxDynamicSharedMemorySize, ATTN_SMEM);
        attr_done = true;
    }

    prep_all_kernel<<<8224, 256>>>(x, Wq, Wk, Wv, Wo);

    dim3 gq(12, MROWS / BM);             // N=1536
    gemm_kernel<0><<<gq, 256, SMEM_TOTAL>>>(nullptr, nullptr);

    dim3 ga(4, NWIN * NHEADS);
    attn_kernel<<<ga, 256, ATTN_SMEM>>>();

    dim3 go(4, MROWS / BM);              // N=512
    gemm_kernel<1><<<go, 256, SMEM_TOTAL>>>(out, bo);
}

// round 13
// speedup vs baseline: 2.5938x; 1.1797x over previous
#include <cuda_runtime.h>
#include <cuda_fp16.h>
#include <math.h>
#include <stdint.h>

#define CDIM   512
#define NHEADS 8
#define DH     64
#define NWIN   32
#define SLEN   512
#define MROWS  (NWIN*SLEN)   // 16384

// ------------------------- device scratch (no allocs) -------------------------
__device__ __align__(16) __half g_xh[MROWS*CDIM];          // gathered x, fp16
__device__ __align__(16) __half g_atth[MROWS*CDIM];        // attention out, fp16
__device__ __align__(16) __half g_W[2048*CDIM];            // [n][k]: 0..1535 [Wq|Wk|Wv]^T, 1536..2047 Wo^T
__device__ __align__(16) __half g_Qh[NWIN*NHEADS*SLEN*DH]; // fp16 single plane
__device__ __align__(16) __half g_Kh[NWIN*NHEADS*SLEN*DH];
__device__ __align__(16) __half g_Vt[NWIN*NHEADS*DH*SLEN]; // transposed [nh][d][t]
__device__ float g_tabc[16*SLEN];
__device__ float g_tabs[16*SLEN];

// ------------------------- helpers -------------------------
__device__ __forceinline__ uint32_t smem_u32(const void* p) {
    uint32_t a;
    asm("{ .reg .u64 t; cvta.to.shared.u64 t, %1; cvt.u32.u64 %0, t; }" : "=r"(a) : "l"(p));
    return a;
}
__device__ __forceinline__ void cpasync16(uint32_t dst, const void* src) {
    asm volatile("cp.async.cg.shared.global [%0], [%1], 16;" :: "r"(dst), "l"(src) : "memory");
}
#define CP_COMMIT() asm volatile("cp.async.commit_group;" ::: "memory")
#define CP_WAIT(n)  asm volatile("cp.async.wait_group %0;" :: "n"(n) : "memory")

__device__ __forceinline__ void ldm_x4(uint32_t& r0, uint32_t& r1, uint32_t& r2, uint32_t& r3, uint32_t a) {
    asm volatile("ldmatrix.sync.aligned.m8n8.x4.shared.b16 {%0,%1,%2,%3}, [%4];"
                 : "=r"(r0), "=r"(r1), "=r"(r2), "=r"(r3) : "r"(a));
}
__device__ __forceinline__ void mma16816(float* d, const uint32_t* a, const uint32_t* b) {
    asm volatile(
        "mma.sync.aligned.m16n8k16.row.col.f32.f16.f16.f32 "
        "{%0,%1,%2,%3}, {%4,%5,%6,%7}, {%8,%9}, {%0,%1,%2,%3};"
        : "+f"(d[0]), "+f"(d[1]), "+f"(d[2]), "+f"(d[3])
        : "r"(a[0]), "r"(a[1]), "r"(a[2]), "r"(a[3]), "r"(b[0]), "r"(b[1]));
}
__device__ __forceinline__ uint32_t pack_h(__half a, __half b) {
    return ((uint32_t)__half_as_ushort(b) << 16) | __half_as_ushort(a);
}
// 128B-pitch XOR swizzle (rows of 64 fp16), ch = 16B segment 0..7
__device__ __forceinline__ uint32_t swz128(int r, int ch) {
    return (uint32_t)(r * 128 + ((ch ^ (r & 7)) << 4));
}

// ------------------------- fused prep kernel -------------------------
// blocks [0,4096): x gather->fp16 (2 float4/thread); [4096,8192): W transpose; [8192,8224): rotary table
__global__ __launch_bounds__(256) void prep_all_kernel(
    const float* __restrict__ x,
    const float* __restrict__ Wq, const float* __restrict__ Wk,
    const float* __restrict__ Wv, const float* __restrict__ Wo)
{
    const int gb = blockIdx.x;
    if (gb < 4096) {
        int t2 = (gb * 256 + threadIdx.x) * 2;
#pragma unroll
        for (int u = 0; u < 2; u++) {
            int id4 = t2 + u;
            int m = id4 >> 7;
            int k4 = (id4 & 127) << 2;
            int nwin = m >> 9, s = m & 511;
            int b = nwin & 1, wb = (nwin >> 1) & 3, hb = nwin >> 3;
            int f = s >> 6, r = (s >> 3) & 7, cc = s & 7;
            const float* src = x + (size_t)((((b*8 + f)*32 + hb*8 + r)*32 + wb*8 + cc)) * CDIM + k4;
            float4 v = *(const float4*)src;
            uint2 hv = { pack_h(__float2half_rn(v.x), __float2half_rn(v.y)),
                         pack_h(__float2half_rn(v.z), __float2half_rn(v.w)) };
            *(uint2*)(g_xh + (size_t)m * CDIM + k4) = hv;
        }
    } else if (gb < 8192) {
        int idx = (gb - 4096) * 256 + threadIdx.x;
        int n = idx & 511;
        int km = idx >> 9;
        int mat = km >> 9, k = km & 511;
        const float* W = (mat == 0) ? Wq : (mat == 1) ? Wk : (mat == 2) ? Wv : Wo;
        float v = W[(size_t)k * CDIM + n];
        g_W[(size_t)(mat * 512 + n) * CDIM + k] = __float2half_rn(v);
    } else {
        int idx = (gb - 8192) * 256 + threadIdx.x;
        if (idx < 16 * SLEN) {
            int jj = idx >> 9, s = idx & 511;
            const float LN = 0.5756462732485114210f;    // ln(10000)/16
            float ang = (float)s * expf(-LN * (float)jj);
            float sn, cs;
            sincosf(ang, &sn, &cs);
            g_tabc[idx] = cs;
            g_tabs[idx] = sn;
        }
    }
}

// ------------------------- mma.sync GEMM (3-stage, BK=64) -------------------------
#define BM 128
#define BN 128
#define BK 64
#define PLSTG (128*128)       // 16384: one operand tile (128 rows x 128B)
#define STAGE (2*PLSTG)       // 32768
#define SA_OFF(st)  ((st)*STAGE)
#define SB_OFF(st)  ((st)*STAGE + PLSTG)
#define SMEM_TOTAL (3*STAGE)  // 98304 -> 2 CTAs/SM

template<int MODE>
__global__ __launch_bounds__(256) void gemm_kernel(float* __restrict__ out,
                                                   const float* __restrict__ bo)
{
    extern __shared__ char smem[];
    const uint32_t sb = smem_u32(smem);
    const int tid  = threadIdx.x;
    const int lane = tid & 31;
    const int wid  = tid >> 5;
    const int warpM = wid >> 1;
    const int warpN = wid & 1;
    const int gid = lane >> 2;
    const int tig = lane & 3;
    const int lrow = lane & 15;
    const int lside = lane >> 4;

    const int m0 = blockIdx.y * BM;
    const int n0 = blockIdx.x * BN;
    const int nrow0 = MODE ? (1536 + n0) : n0;
    const __half* Ap = MODE ? g_atth : g_xh;

    float acc[2][8][4];
#pragma unroll
    for (int i = 0; i < 2; i++)
#pragma unroll
        for (int j = 0; j < 8; j++)
#pragma unroll
            for (int t = 0; t < 4; t++) acc[i][j][t] = 0.f;

    auto load_chunk = [&](int c, int st) {
        const int k0 = c * BK;
#pragma unroll
        for (int i = tid; i < 1024; i += 256) {        // A: 128 rows x 8 segs
            int rr = i >> 3, ch = i & 7;
            const __half* src = Ap + (size_t)(m0 + rr) * CDIM + k0 + ch * 8;
            cpasync16(sb + SA_OFF(st) + swz128(rr, ch), src);
        }
#pragma unroll
        for (int i = tid; i < 1024; i += 256) {        // B: 128 rows x 8 segs
            int rr = i >> 3, ch = i & 7;
            const __half* src = g_W + (size_t)(nrow0 + rr) * CDIM + k0 + ch * 8;
            cpasync16(sb + SB_OFF(st) + swz128(rr, ch), src);
        }
        CP_COMMIT();
    };

    load_chunk(0, 0);
    load_chunk(1, 1);

    const int NCH = CDIM / BK;   // 8

    for (int c = 0; c < NCH; c++) {
        if (c == NCH - 1) CP_WAIT(0); else CP_WAIT(1);
        __syncthreads();
        if (c + 2 < NCH) load_chunk(c + 2, (c + 2) % 3);
        const int st = c % 3;
#pragma unroll
        for (int ks = 0; ks < 4; ks++) {                // 4 k16 steps per 64-chunk
            const int chq = ks * 2 + lside;
            uint32_t ah[2][4];
#pragma unroll
            for (int mt = 0; mt < 2; mt++) {
                int ra = warpM*32 + mt*16 + lrow;
                ldm_x4(ah[mt][0], ah[mt][1], ah[mt][2], ah[mt][3],
                       sb + SA_OFF(st) + swz128(ra, chq));
            }
            uint32_t bh[8][2];
#pragma unroll
            for (int ntp = 0; ntp < 4; ntp++) {
                int rb = warpN*64 + ntp*16 + lrow;
                ldm_x4(bh[2*ntp][0], bh[2*ntp+1][0], bh[2*ntp][1], bh[2*ntp+1][1],
                       sb + SB_OFF(st) + swz128(rb, chq));
            }
#pragma unroll
            for (int mt = 0; mt < 2; mt++)
#pragma unroll
                for (int nt = 0; nt < 8; nt++) mma16816(acc[mt][nt], ah[mt], bh[nt]);
        }
    }

    const int mwbase = m0 + warpM * 32;
    const int cwbase = n0 + warpN * 64;

#pragma unroll
    for (int mt = 0; mt < 2; mt++) {
#pragma unroll
        for (int nt = 0; nt < 8; nt++) {
            const int g = cwbase + nt * 8 + tig * 2;
            if (MODE == 0) {
                const int mat = g >> 9;
                const int cc = g & 511;
                const int head = cc >> 6;
                const int d = cc & 63;
#pragma unroll
                for (int half = 0; half < 2; half++) {
                    const int row = mwbase + mt * 16 + gid + half * 8;
                    const int nw = row >> 9;
                    const int s  = row & 511;
                    float v0 = acc[mt][nt][half * 2];
                    float v1 = acc[mt][nt][half * 2 + 1];
                    if (mat < 2 && d < 32) {
                        const int j0 = d >> 1;
                        float cs = g_tabc[j0 * 512 + s];
                        float sn = g_tabs[j0 * 512 + s];
                        float w0 = v0 * cs - v1 * sn;
                        float w1 = v1 * cs + v0 * sn;
                        v0 = w0; v1 = w1;
                    }
                    const int nhh = nw * NHEADS + head;
                    uint32_t hv = pack_h(__float2half_rn(v0), __float2half_rn(v1));
                    if (mat == 0) {
                        *(uint32_t*)(g_Qh + ((size_t)nhh * SLEN + s) * DH + d) = hv;
                    } else if (mat == 1) {
                        *(uint32_t*)(g_Kh + ((size_t)nhh * SLEN + s) * DH + d) = hv;
                    } else {
                        size_t vb = ((size_t)nhh * DH + d) * SLEN + s;
                        g_Vt[vb]        = __float2half_rn(v0);
                        g_Vt[vb + SLEN] = __float2half_rn(v1);
                    }
                }
            } else {
                const float2 bias = *(const float2*)(bo + g);
#pragma unroll
                for (int half = 0; half < 2; half++) {
                    const int row = mwbase + mt * 16 + gid + half * 8;
                    const int nwv = row >> 9, ss = row & 511;
                    const int b = nwv & 1, wb = (nwv >> 1) & 3, hb = nwv >> 3;
                    const int fr = ss >> 6, rr = (ss >> 3) & 7, c2 = ss & 7;
                    const size_t obase = ((size_t)b * (8*32*32) + (size_t)fr * (32*32)
                                        + (size_t)(hb*8 + rr) * 32 + (wb*8 + c2)) * CDIM;
                    float2 v = { acc[mt][nt][half*2] + bias.x,
                                 acc[mt][nt][half*2 + 1] + bias.y };
                    *(float2*)(out + obase + g) = v;
                }
            }
        }
    }
}

// ------------------------- flash attention (fp16 single-plane Q/K/V/P) -------------------------
// smem: Q 16KB | 3 stages x (K 8KB + V 8KB) | P 16KB = 81920 -> 2 CTAs/SM
#define AQ_OFF       0
#define AK_OFF(st)   (16384 + (st) * 16384)
#define AV_OFF(st)   (16384 + (st) * 16384 + 8192)
#define APP_OFF      65536
#define ATTN_SMEM    81920

__global__ __launch_bounds__(256) void attn_kernel()
{
    extern __shared__ char smem[];
    const uint32_t sb = smem_u32(smem);
    const int qt = blockIdx.x;
    const int nh = blockIdx.y;
    const int tid = threadIdx.x;
    const int lane = tid & 31;
    const int wid = tid >> 5;
    const int gid = lane >> 2;
    const int tig = lane & 3;
    const int lrow = lane & 15;
    const int lside = lane >> 4;

    // Q tile (128 x 64), swizzled 128B rows
    {
        const size_t qbase = ((size_t)nh * SLEN + qt * 128) * DH;
#pragma unroll
        for (int i = tid; i < 1024; i += 256) {
            int r = i >> 3, ch = i & 7;
            cpasync16(sb + AQ_OFF + swz128(r, ch), g_Qh + qbase + (size_t)r * DH + ch * 8);
        }
        CP_COMMIT();
    }

    const int nkt = 2 * qt + 2;

    auto load_kv = [&](int kt, int st) {
#pragma unroll
        for (int i = tid; i < 1024; i += 256) {
            if (i < 512) {                        // K tile [t][d]
                int r = i >> 3, ch = i & 7;
                cpasync16(sb + AK_OFF(st) + swz128(r, ch),
                          g_Kh + ((size_t)nh * SLEN + kt * 64 + r) * DH + ch * 8);
            } else {                              // V^T tile [d][t]
                int j = i - 512;
                int r = j >> 3, ch = j & 7;
                cpasync16(sb + AV_OFF(st) + swz128(r, ch),
                          g_Vt + ((size_t)nh * DH + r) * SLEN + kt * 64 + ch * 8);
            }
        }
        CP_COMMIT();
    };

    load_kv(0, 0);
    if (nkt > 1) load_kv(1, 1);

    float accO[8][4];
#pragma unroll
    for (int j = 0; j < 8; j++)
#pragma unroll
        for (int t = 0; t < 4; t++) accO[j][t] = 0.f;
    float lsum0 = 0.f, lsum1 = 0.f;

    const int qrow0 = qt * 128 + wid * 16;

    for (int kt = 0; kt < nkt; kt++) {
        if (kt == nkt - 1) CP_WAIT(0); else CP_WAIT(1);
        __syncthreads();
        if (kt + 2 < nkt) load_kv(kt + 2, (kt + 2) % 3);
        const int st = kt % 3;

        // ---- S = Q K^T ----
        float accS[8][4];
#pragma unroll
        for (int j = 0; j < 8; j++)
#pragma unroll
            for (int t = 0; t < 4; t++) accS[j][t] = 0.f;

#pragma unroll
        for (int k4 = 0; k4 < 4; k4++) {
            const int chq = k4 * 2 + lside;
            uint32_t qh[4];
            ldm_x4(qh[0], qh[1], qh[2], qh[3], sb + AQ_OFF + swz128(wid*16 + lrow, chq));
            uint32_t kh[8][2];
#pragma unroll
            for (int ntp = 0; ntp < 4; ntp++) {
                ldm_x4(kh[2*ntp][0], kh[2*ntp+1][0], kh[2*ntp][1], kh[2*ntp+1][1],
                       sb + AK_OFF(st) + swz128(ntp*16 + lrow, chq));
            }
#pragma unroll
            for (int nt = 0; nt < 8; nt++) mma16816(accS[nt], qh, kh[nt]);
        }

        // ---- exp + causal + l + fp16 P (warp-private rows, swizzled) ----
#pragma unroll
        for (int nt = 0; nt < 8; nt++) {
#pragma unroll
            for (int half = 0; half < 2; half++) {
                const int row = qrow0 + gid + half * 8;
                const int col0 = kt * 64 + nt * 8 + tig * 2;
                float s0 = accS[nt][half*2]     * 0.125f;
                float s1 = accS[nt][half*2 + 1] * 0.125f;
                float p0 = (col0     <= row) ? __expf(s0) : 0.f;
                float p1 = (col0 + 1 <= row) ? __expf(s1) : 0.f;
                if (half) lsum1 += p0 + p1; else lsum0 += p0 + p1;
                const int r = wid*16 + gid + half*8;
                uint32_t off = (uint32_t)(r * 128 + ((nt ^ (r & 7)) << 4) + tig * 4);
                *(uint32_t*)(smem + APP_OFF + off) =
                    pack_h(__float2half_rn(p0), __float2half_rn(p1));
            }
        }
        __syncwarp();   // P rows are warp-private

        // ---- O += P V ----
#pragma unroll
        for (int k4 = 0; k4 < 4; k4++) {
            const int chq = k4 * 2 + lside;
            uint32_t ph[4];
            ldm_x4(ph[0], ph[1], ph[2], ph[3], sb + APP_OFF + swz128(wid*16 + lrow, chq));
            uint32_t vh[8][2];
#pragma unroll
            for (int ntp = 0; ntp < 4; ntp++) {
                ldm_x4(vh[2*ntp][0], vh[2*ntp+1][0], vh[2*ntp][1], vh[2*ntp+1][1],
                       sb + AV_OFF(st) + swz128(ntp*16 + lrow, chq));
            }
#pragma unroll
            for (int nt = 0; nt < 8; nt++) mma16816(accO[nt], ph, vh[nt]);
        }
    }

    // ---- finalize ----
    lsum0 += __shfl_xor_sync(0xFFFFFFFF, lsum0, 1);
    lsum0 += __shfl_xor_sync(0xFFFFFFFF, lsum0, 2);
    lsum1 += __shfl_xor_sync(0xFFFFFFFF, lsum1, 1);
    lsum1 += __shfl_xor_sync(0xFFFFFFFF, lsum1, 2);
    const float inv0 = 1.f / lsum0;
    const float inv1 = 1.f / lsum1;

    const int nwn = nh >> 3, hh = nh & 7;
#pragma unroll
    for (int half = 0; half < 2; half++) {
        const int srow = qrow0 + gid + half * 8;
        const float inv = half ? inv1 : inv0;
        const size_t mrow = (size_t)nwn * SLEN + srow;
#pragma unroll
        for (int nt = 0; nt < 8; nt++) {
            const int d = nt * 8 + tig * 2;
            float v0 = accO[nt][half*2]     * inv;
            float v1 = accO[nt][half*2 + 1] * inv;
            size_t base = mrow * CDIM + hh * DH + d;
            *(uint32_t*)(g_atth + base) = pack_h(__float2half_rn(v0), __float2half_rn(v1));
        }
    }
}

// ------------------------- launch -------------------------
extern "C" void kernel_launch(void* const* d_in, const int* in_sizes, int n_in,
                              void* d_out, int out_size)
{
    const float* x  = (const float*)d_in[0];
    const float* Wq = (const float*)d_in[1];
    const float* Wk = (const float*)d_in[2];
    const float* Wv = (const float*)d_in[3];
    const float* Wo = (const float*)d_in[4];
    const float* bo = (const float*)d_in[5];
    float* out = (float*)d_out;
    (void)in_sizes; (void)n_in; (void)out_size;

    static bool attr_done = false;
    if (!attr_done) {
        cudaFuncSetAttribute(gemm_kernel<0>, cudaFuncAttributeMaxDynamicSharedMemorySize, SMEM_TOTAL);
        cudaFuncSetAttribute(gemm_kernel<1>, cudaFuncAttributeMaxDynamicSharedMemorySize, SMEM_TOTAL);
        cudaFuncSetAttribute(attn_kernel, cudaFuncAttributeMaxDynamicSharedMemorySize, ATTN_SMEM);
        attr_done = true;
    }

    prep_all_kernel<<<8224, 256>>>(x, Wq, Wk, Wv, Wo);

    dim3 gq(12, MROWS / BM);             // N=1536
    gemm_kernel<0><<<gq, 256, SMEM_TOTAL>>>(nullptr, nullptr);

    dim3 ga(4, NWIN * NHEADS);
    attn_kernel<<<ga, 256, ATTN_SMEM>>>();

    dim3 go(4, MROWS / BM);              // N=512
    gemm_kernel<1><<<go, 256, SMEM_TOTAL>>>(out, bo);
}